// round 2
// baseline (speedup 1.0000x reference)
#include <cuda_runtime.h>
#include <math.h>
#include <stdint.h>

#define LL    1024
#define BSZ   8
#define DQK   256
#define DEXP  512
#define NHEAD 8
#define HDIM  64
#define DATT  32
#define MROWS (LL*BSZ)   // 8192
#define HALF_OUT 256

// ---------------- scratch (no allocations allowed) ----------------
__device__ float g_Qp[MROWS*DQK];   // linear_QK output (unscaled)
__device__ float g_Vc[MROWS*DEXP];  // gated V projection
__device__ float g_Uc[MROWS*DEXP];  // gated U projection
__device__ float g_G [MROWS*DEXP];  // U-gated attention output
__device__ float g_Y [MROWS*DEXP];  // conv output

// ---------------- generic tiled GEMM + bias: C[M,N] = A[M,K]@B[K,N] + bias ----------------
__global__ __launch_bounds__(256) void gemm_bias_kernel(
    const float* __restrict__ A, const float* __restrict__ B,
    const float* __restrict__ bias, float* __restrict__ C,
    int M, int N, int K)
{
    __shared__ float As[16][65];
    __shared__ float Bs[16][64];
    const int m0 = blockIdx.y * 64, n0 = blockIdx.x * 64;
    const int tid = threadIdx.x;
    const int tx = tid & 15, ty = tid >> 4;
    float acc[4][4] = {};

    for (int k0 = 0; k0 < K; k0 += 16) {
        #pragma unroll
        for (int idx = tid; idx < 64*16; idx += 256) {
            int r = idx >> 4, kk = idx & 15;
            As[kk][r] = A[(size_t)(m0 + r) * K + k0 + kk];
        }
        #pragma unroll
        for (int idx = tid; idx < 16*64; idx += 256) {
            int kk = idx >> 6, c = idx & 63;
            Bs[kk][c] = B[(size_t)(k0 + kk) * N + n0 + c];
        }
        __syncthreads();
        #pragma unroll
        for (int kk = 0; kk < 16; kk++) {
            float a[4], b[4];
            #pragma unroll
            for (int i = 0; i < 4; i++) a[i] = As[kk][ty + 16*i];
            #pragma unroll
            for (int j = 0; j < 4; j++) b[j] = Bs[kk][tx + 16*j];
            #pragma unroll
            for (int i = 0; i < 4; i++)
                #pragma unroll
                for (int j = 0; j < 4; j++)
                    acc[i][j] += a[i] * b[j];
        }
        __syncthreads();
    }
    #pragma unroll
    for (int i = 0; i < 4; i++) {
        int r = m0 + ty + 16*i;
        #pragma unroll
        for (int j = 0; j < 4; j++) {
            int c = n0 + tx + 16*j;
            C[(size_t)r * N + c] = acc[i][j] + bias[c];
        }
    }
}

// ---------------- gated half-projection + SiLU ----------------
// out[m, c] for c = h*64+j:  j<32 -> (X[:, :128] @ W1[:, h*32+j] + b1),  j>=32 -> (X[:,128:] @ W2[:, h*32+j-32] + b2)
// then y * sigmoid(y). 32-col tiles are half-uniform.
__global__ __launch_bounds__(256) void gated_proj_kernel(
    const float* __restrict__ X,   // [MROWS, 256]
    const float* __restrict__ W1, const float* __restrict__ b1,
    const float* __restrict__ W2, const float* __restrict__ b2,
    float* __restrict__ Yout)      // [MROWS, 512]
{
    __shared__ float As[16][65];   // transposed A tile: [kk][row]
    __shared__ float Bs[16][32];
    const int c0   = blockIdx.x * 32;
    const int head = c0 >> 6;
    const int is2  = (c0 >> 5) & 1;
    const float* W  = is2 ? W2 : W1;
    const float* bb = is2 ? b2 : b1;
    const int wc0 = head * 32;
    const float* Ain = X + (is2 ? 128 : 0);
    const int m0 = blockIdx.y * 64;
    const int tid = threadIdx.x;
    const int tx = tid & 31, ty = tid >> 5;   // tx: col, ty: row group
    float acc[8] = {};

    for (int k0 = 0; k0 < 128; k0 += 16) {
        #pragma unroll
        for (int idx = tid; idx < 64*16; idx += 256) {
            int r = idx >> 4, kk = idx & 15;
            As[kk][r] = Ain[(size_t)(m0 + r) * 256 + k0 + kk];
        }
        #pragma unroll
        for (int idx = tid; idx < 16*32; idx += 256) {
            int kk = idx >> 5, c = idx & 31;
            Bs[kk][c] = W[(size_t)(k0 + kk) * HALF_OUT + wc0 + c];
        }
        __syncthreads();
        #pragma unroll
        for (int kk = 0; kk < 16; kk++) {
            float bv = Bs[kk][tx];
            #pragma unroll
            for (int i = 0; i < 8; i++)
                acc[i] += As[kk][ty + 8*i] * bv;
        }
        __syncthreads();
    }
    float bias = bb[wc0 + tx];
    #pragma unroll
    for (int i = 0; i < 8; i++) {
        int r = m0 + ty + 8*i;
        float v = acc[i] + bias;
        float y = v / (1.0f + __expf(-v));   // silu
        Yout[(size_t)r * DEXP + c0 + tx] = y;
    }
}

// ---------------- fused attention: scores -> softmax -> attn write -> AV -> U-gate ----------------
// grid: (32 row-tiles, NHEAD, BSZ), 256 threads, dynamic smem.
__global__ __launch_bounds__(256) void attn_kernel(
    const float* __restrict__ Qp, const float* __restrict__ Vc,
    const float* __restrict__ Uc, float* __restrict__ attn_out,  // may be null
    float* __restrict__ Gout)
{
    extern __shared__ float sm[];
    float* S  = sm;                   // [32][1024]
    float* Qs = S  + 32*1024;         // [32][32]
    float* Kt = Qs + 32*32;           // [64][33]
    float* Vt = Kt + 64*33;           // [64][65]

    const int r0 = blockIdx.x * 32;
    const int h  = blockIdx.y, b = blockIdx.z;
    const int tid = threadIdx.x;
    const int tx = tid & 31, ty = tid >> 5;
    const float scale = 0.17677669529663687f;   // 1/sqrt(32)

    // Q tile (pre-scaled)
    for (int idx = tid; idx < 32*32; idx += 256) {
        int r = idx >> 5, c = idx & 31;
        Qs[idx] = Qp[((size_t)(r0 + r) * BSZ + b) * DQK + h*DATT + c] * scale;
    }

    // ---- scores into S ----
    for (int kt = 0; kt < 16; kt++) {
        __syncthreads();
        for (int idx = tid; idx < 64*32; idx += 256) {
            int r = idx >> 5, c = idx & 31;
            Kt[r*33 + c] = Qp[((size_t)(kt*64 + r) * BSZ + b) * DQK + h*DATT + c];
        }
        __syncthreads();
        float acc[4][2] = {};
        #pragma unroll
        for (int kd = 0; kd < 32; kd++) {
            float q[4];
            #pragma unroll
            for (int i = 0; i < 4; i++) q[i] = Qs[(ty + 8*i)*32 + kd];
            float k0 = Kt[tx*33 + kd];
            float k1 = Kt[(tx + 32)*33 + kd];
            #pragma unroll
            for (int i = 0; i < 4; i++) { acc[i][0] += q[i]*k0; acc[i][1] += q[i]*k1; }
        }
        #pragma unroll
        for (int i = 0; i < 4; i++) {
            S[(ty + 8*i)*1024 + kt*64 + tx]      = acc[i][0];
            S[(ty + 8*i)*1024 + kt*64 + tx + 32] = acc[i][1];
        }
    }
    __syncthreads();

    // ---- softmax per row (warp per row, 4 rows/warp) + attn write ----
    {
        const int warp = ty, lane = tx;
        for (int rr = 0; rr < 4; rr++) {
            int r = warp + 8*rr;
            float* row = S + r*1024;
            float m = -1e30f;
            for (int k = lane; k < 1024; k += 32) m = fmaxf(m, row[k]);
            #pragma unroll
            for (int o = 16; o; o >>= 1) m = fmaxf(m, __shfl_xor_sync(0xffffffffu, m, o));
            float s = 0.f;
            for (int k = lane; k < 1024; k += 32) {
                float e = __expf(row[k] - m);
                row[k] = e; s += e;
            }
            #pragma unroll
            for (int o = 16; o; o >>= 1) s += __shfl_xor_sync(0xffffffffu, s, o);
            float inv = 1.0f / s;
            float* g = attn_out ? attn_out + (((size_t)(b*NHEAD + h) * LL + (r0 + r)) * LL) : nullptr;
            for (int k = lane; k < 1024; k += 32) {
                float p = row[k] * inv;
                row[k] = p;
                if (g) g[k] = p;
            }
        }
    }
    __syncthreads();

    // ---- AV + U-gate ----
    float acc[4][2] = {};
    for (int vt = 0; vt < 16; vt++) {
        for (int idx = tid; idx < 64*64; idx += 256) {
            int r = idx >> 6, c = idx & 63;
            Vt[r*65 + c] = Vc[((size_t)(vt*64 + r) * BSZ + b) * DEXP + h*HDIM + c];
        }
        __syncthreads();
        #pragma unroll 8
        for (int kk = 0; kk < 64; kk++) {
            float p[4];
            #pragma unroll
            for (int i = 0; i < 4; i++) p[i] = S[(ty + 8*i)*1024 + vt*64 + kk];
            float v0 = Vt[kk*65 + tx];
            float v1 = Vt[kk*65 + tx + 32];
            #pragma unroll
            for (int i = 0; i < 4; i++) { acc[i][0] += p[i]*v0; acc[i][1] += p[i]*v1; }
        }
        __syncthreads();
    }
    #pragma unroll
    for (int i = 0; i < 4; i++) {
        int r = r0 + ty + 8*i;
        int c = h*HDIM + tx;
        size_t base = ((size_t)r * BSZ + b) * DEXP;
        Gout[base + c]      = acc[i][0] * Uc[base + c];
        Gout[base + c + 32] = acc[i][1] * Uc[base + c + 32];
    }
}

// ---------------- depthwise 5x5 conv on 32x32 grid ----------------
// grid: (16 channel tiles, BSZ), 256 threads, dynamic smem.
__global__ __launch_bounds__(256) void dwconv_kernel(
    const float* __restrict__ X, const float* __restrict__ Wc, float* __restrict__ Y)
{
    extern __shared__ float sm[];
    float* xs = sm;             // [1024][33] (32 channels, pitch 33)
    float* ws = sm + 1024*33;   // [32][25]
    const int c0 = blockIdx.x * 32, b = blockIdx.y;
    const int tid = threadIdx.x;

    for (int idx = tid; idx < 1024*32; idx += 256) {
        int t = idx >> 5, c = idx & 31;
        xs[t*33 + c] = X[((size_t)t * BSZ + b) * DEXP + c0 + c];
    }
    for (int idx = tid; idx < 32*25; idx += 256) {
        int c = idx / 25, t = idx % 25;
        ws[c*25 + t] = Wc[(size_t)(c0 + c) * 25 + t];
    }
    __syncthreads();

    const int c = tid & 31, pr = tid >> 5;
    for (int s = 0; s < 128; s++) {
        int pos = pr + 8*s;
        int i = pos >> 5, j = pos & 31;
        float acc = 0.f;
        #pragma unroll
        for (int di = 0; di < 5; di++) {
            int ii = i + di - 2;
            if (ii < 0 || ii >= 32) continue;
            #pragma unroll
            for (int dj = 0; dj < 5; dj++) {
                int jj = j + dj - 2;
                if (jj < 0 || jj >= 32) continue;
                acc += xs[(ii*32 + jj)*33 + c] * ws[c*25 + di*5 + dj];
            }
        }
        Y[((size_t)pos * BSZ + b) * DEXP + c0 + c] = acc;
    }
}

// ---------------- launch ----------------
extern "C" void kernel_launch(void* const* d_in, const int* in_sizes, int n_in,
                              void* d_out, int out_size)
{
    const float* Q   = (const float*)d_in[0];
    // d_in[1] = K is unused by the reference (use_linear path discards it)
    const float* V   = (const float*)d_in[2];
    const float* U   = (const float*)d_in[3];
    const float* Wqk = (const float*)d_in[4];
    const float* bqk = (const float*)d_in[5];
    const float* Wv1 = (const float*)d_in[6];
    const float* bv1 = (const float*)d_in[7];
    const float* Wv2 = (const float*)d_in[8];
    const float* bv2 = (const float*)d_in[9];
    const float* Wu1 = (const float*)d_in[10];
    const float* bu1 = (const float*)d_in[11];
    const float* Wu2 = (const float*)d_in[12];
    const float* bu2 = (const float*)d_in[13];
    const float* Wcv = (const float*)d_in[14];
    const float* Wp  = (const float*)d_in[15];
    const float* bp  = (const float*)d_in[16];

    float* out  = (float*)d_out;
    float* attn = (out_size > MROWS*DQK) ? out + (size_t)MROWS*DQK : nullptr;

    float *Qp, *Vc, *Uc, *G, *Y;
    cudaGetSymbolAddress((void**)&Qp, g_Qp);
    cudaGetSymbolAddress((void**)&Vc, g_Vc);
    cudaGetSymbolAddress((void**)&Uc, g_Uc);
    cudaGetSymbolAddress((void**)&G,  g_G);
    cudaGetSymbolAddress((void**)&Y,  g_Y);

    const size_t ATTN_SMEM = (size_t)(32*1024 + 32*32 + 64*33 + 64*65) * sizeof(float); // 160,256 B
    const size_t CONV_SMEM = (size_t)(1024*33 + 32*25) * sizeof(float);                 // 138,368 B
    cudaFuncSetAttribute(attn_kernel,   cudaFuncAttributeMaxDynamicSharedMemorySize, (int)ATTN_SMEM);
    cudaFuncSetAttribute(dwconv_kernel, cudaFuncAttributeMaxDynamicSharedMemorySize, (int)CONV_SMEM);

    // 1) Qp = Q @ Wqk + bqk
    {
        dim3 grid(DQK/64, MROWS/64);
        gemm_bias_kernel<<<grid, 256>>>(Q, Wqk, bqk, Qp, MROWS, DQK, DQK);
    }
    // 2) Vc, Uc gated projections
    {
        dim3 grid(16, MROWS/64);
        gated_proj_kernel<<<grid, 256>>>(V, Wv1, bv1, Wv2, bv2, Vc);
        gated_proj_kernel<<<grid, 256>>>(U, Wu1, bu1, Wu2, bu2, Uc);
    }
    // 3) attention (+ attn output + U-gate)
    {
        dim3 grid(LL/32, NHEAD, BSZ);
        attn_kernel<<<grid, 256, ATTN_SMEM>>>(Qp, Vc, Uc, attn, G);
    }
    // 4) depthwise conv
    {
        dim3 grid(16, BSZ);
        dwconv_kernel<<<grid, 256, CONV_SMEM>>>(G, Wcv, Y);
    }
    // 5) outputs = Y @ Wp + bp
    {
        dim3 grid(DQK/64, MROWS/64);
        gemm_bias_kernel<<<grid, 256>>>(Y, Wp, bp, out, MROWS, DQK, DEXP);
    }
}

// round 4
// speedup vs baseline: 1.6641x; 1.6641x over previous
#include <cuda_runtime.h>
#include <math.h>
#include <stdint.h>

#define LL    1024
#define BSZ   8
#define DQK   256
#define DEXP  512
#define NHEAD 8
#define HDIM  64
#define DATT  32
#define MROWS (LL*BSZ)   // 8192
#define HALF_OUT 256
#define SPITCH 1028      // S row pitch (floats)
#define VPITCH 72        // V-tile pitch: float4-aligned, conflict-free frag reads

// ---------------- scratch (no allocations allowed) ----------------
__device__ __align__(256) float g_Qp[MROWS*DQK];
__device__ __align__(256) float g_Vc[MROWS*DEXP];
__device__ __align__(256) float g_Uc[MROWS*DEXP];
__device__ __align__(256) float g_G [MROWS*DEXP];
__device__ __align__(256) float g_Y [MROWS*DEXP];

// ---------------- tf32 helpers ----------------
__device__ __forceinline__ void tf32_split(float x, uint32_t& hi, uint32_t& lo) {
    uint32_t h;
    asm("cvt.rna.tf32.f32 %0, %1;" : "=r"(h) : "f"(x));
    float hf = __uint_as_float(h);
    float l = x - hf;
    uint32_t lr;
    asm("cvt.rna.tf32.f32 %0, %1;" : "=r"(lr) : "f"(l));
    hi = h; lo = lr;
}

__device__ __forceinline__ void mma_tf32(float* c, const uint32_t* a, const uint32_t* b) {
    asm volatile(
        "mma.sync.aligned.m16n8k8.row.col.f32.tf32.tf32.f32 "
        "{%0,%1,%2,%3},{%4,%5,%6,%7},{%8,%9},{%0,%1,%2,%3};"
        : "+f"(c[0]), "+f"(c[1]), "+f"(c[2]), "+f"(c[3])
        : "r"(a[0]), "r"(a[1]), "r"(a[2]), "r"(a[3]), "r"(b[0]), "r"(b[1]));
}

// ---------------- generic tiled GEMM + bias ----------------
__global__ __launch_bounds__(256) void gemm_bias_kernel(
    const float* __restrict__ A, const float* __restrict__ B,
    const float* __restrict__ bias, float* __restrict__ C,
    int M, int N, int K)
{
    __shared__ float As[16][65];
    __shared__ float Bs[16][64];
    const int m0 = blockIdx.y * 64, n0 = blockIdx.x * 64;
    const int tid = threadIdx.x;
    const int tx = tid & 15, ty = tid >> 4;
    float acc[4][4] = {};

    for (int k0 = 0; k0 < K; k0 += 16) {
        #pragma unroll
        for (int idx = tid; idx < 64*16; idx += 256) {
            int r = idx >> 4, kk = idx & 15;
            As[kk][r] = A[(size_t)(m0 + r) * K + k0 + kk];
        }
        #pragma unroll
        for (int idx = tid; idx < 16*64; idx += 256) {
            int kk = idx >> 6, c = idx & 63;
            Bs[kk][c] = B[(size_t)(k0 + kk) * N + n0 + c];
        }
        __syncthreads();
        #pragma unroll
        for (int kk = 0; kk < 16; kk++) {
            float a[4], b[4];
            #pragma unroll
            for (int i = 0; i < 4; i++) a[i] = As[kk][ty + 16*i];
            #pragma unroll
            for (int j = 0; j < 4; j++) b[j] = Bs[kk][tx + 16*j];
            #pragma unroll
            for (int i = 0; i < 4; i++)
                #pragma unroll
                for (int j = 0; j < 4; j++)
                    acc[i][j] += a[i] * b[j];
        }
        __syncthreads();
    }
    #pragma unroll
    for (int i = 0; i < 4; i++) {
        int r = m0 + ty + 16*i;
        #pragma unroll
        for (int j = 0; j < 4; j++) {
            int c = n0 + tx + 16*j;
            C[(size_t)r * N + c] = acc[i][j] + bias[c];
        }
    }
}

// ---------------- gated half-projection + SiLU ----------------
__global__ __launch_bounds__(256) void gated_proj_kernel(
    const float* __restrict__ X,
    const float* __restrict__ W1, const float* __restrict__ b1,
    const float* __restrict__ W2, const float* __restrict__ b2,
    float* __restrict__ Yout)
{
    __shared__ float As[16][65];
    __shared__ float Bs[16][32];
    const int c0   = blockIdx.x * 32;
    const int head = c0 >> 6;
    const int is2  = (c0 >> 5) & 1;
    const float* W  = is2 ? W2 : W1;
    const float* bb = is2 ? b2 : b1;
    const int wc0 = head * 32;
    const float* Ain = X + (is2 ? 128 : 0);
    const int m0 = blockIdx.y * 64;
    const int tid = threadIdx.x;
    const int tx = tid & 31, ty = tid >> 5;
    float acc[8] = {};

    for (int k0 = 0; k0 < 128; k0 += 16) {
        #pragma unroll
        for (int idx = tid; idx < 64*16; idx += 256) {
            int r = idx >> 4, kk = idx & 15;
            As[kk][r] = Ain[(size_t)(m0 + r) * 256 + k0 + kk];
        }
        #pragma unroll
        for (int idx = tid; idx < 16*32; idx += 256) {
            int kk = idx >> 5, c = idx & 31;
            Bs[kk][c] = W[(size_t)(k0 + kk) * HALF_OUT + wc0 + c];
        }
        __syncthreads();
        #pragma unroll
        for (int kk = 0; kk < 16; kk++) {
            float bv = Bs[kk][tx];
            #pragma unroll
            for (int i = 0; i < 8; i++)
                acc[i] += As[kk][ty + 8*i] * bv;
        }
        __syncthreads();
    }
    float bias = bb[wc0 + tx];
    #pragma unroll
    for (int i = 0; i < 8; i++) {
        int r = m0 + ty + 8*i;
        float v = acc[i] + bias;
        float y = v / (1.0f + __expf(-v));
        Yout[(size_t)r * DEXP + c0 + tx] = y;
    }
}

// ---------------- fused attention (tensor-core tf32, 3xTF32) ----------------
// grid: (32 row-tiles, NHEAD, BSZ), 256 threads = 8 warps.
// smem: S[32][SPITCH] | buf[64*VPITCH] | Qbuf[32][33]
__global__ __launch_bounds__(256) void attn_kernel(
    const float* __restrict__ Qp, const float* __restrict__ Vc,
    const float* __restrict__ Uc, float* __restrict__ attn_out,
    float* __restrict__ Gout)
{
    extern __shared__ float sm[];
    float* S    = sm;                  // 32 * SPITCH
    float* buf  = S + 32*SPITCH;       // 64*VPITCH (Vbuf) >= 64*33 (Kbuf)
    float* Qbuf = buf + 64*VPITCH;     // 32*33

    const int r0 = blockIdx.x * 32;
    const int h  = blockIdx.y, b = blockIdx.z;
    const int tid  = threadIdx.x;
    const int lane = tid & 31;
    const int w    = tid >> 5;
    const float scale = 0.17677669529663687f;   // 1/sqrt(32)

    // ---- load Q tile (scaled); prefetch K stage 0 ----
    #pragma unroll
    for (int i = 0; i < 4; i++) {
        int idx = 256*i + tid;
        int r = idx >> 5, d = idx & 31;
        Qbuf[r*33 + d] = Qp[((size_t)(r0 + r) * BSZ + b) * DQK + h*DATT + d] * scale;
    }
    float kreg[8];
    #pragma unroll
    for (int i = 0; i < 8; i++) {
        int idx = 256*i + tid;
        int key = idx >> 5, d = idx & 31;
        kreg[i] = Qp[((size_t)key * BSZ + b) * DQK + h*DATT + d];
    }
    __syncthreads();

    // ---- Q fragments (hi/lo) ----
    uint32_t qa_hi[2][4][4], qa_lo[2][4][4];
    #pragma unroll
    for (int mt = 0; mt < 2; mt++) {
        int r = mt*16 + (lane >> 2);
        #pragma unroll
        for (int ks = 0; ks < 4; ks++) {
            int d = ks*8 + (lane & 3);
            tf32_split(Qbuf[r*33 + d],       qa_hi[mt][ks][0], qa_lo[mt][ks][0]);
            tf32_split(Qbuf[(r+8)*33 + d],   qa_hi[mt][ks][1], qa_lo[mt][ks][1]);
            tf32_split(Qbuf[r*33 + d + 4],   qa_hi[mt][ks][2], qa_lo[mt][ks][2]);
            tf32_split(Qbuf[(r+8)*33 + d+4], qa_hi[mt][ks][3], qa_lo[mt][ks][3]);
        }
    }

    // ---- phase 1: scores ----
    for (int kt = 0; kt < 16; kt++) {
        #pragma unroll
        for (int i = 0; i < 8; i++) {
            int idx = 256*i + tid;
            buf[(idx >> 5)*33 + (idx & 31)] = kreg[i];
        }
        __syncthreads();
        if (kt < 15) {
            int base = (kt + 1) * 64;
            #pragma unroll
            for (int i = 0; i < 8; i++) {
                int idx = 256*i + tid;
                int key = base + (idx >> 5), d = idx & 31;
                kreg[i] = Qp[((size_t)key * BSZ + b) * DQK + h*DATT + d];
            }
        }
        uint32_t bh[4][2], bl[4][2];
        {
            int key = w*8 + (lane >> 2);
            #pragma unroll
            for (int ks = 0; ks < 4; ks++) {
                int d = ks*8 + (lane & 3);
                tf32_split(buf[key*33 + d],     bh[ks][0], bl[ks][0]);
                tf32_split(buf[key*33 + d + 4], bh[ks][1], bl[ks][1]);
            }
        }
        __syncthreads();
        #pragma unroll
        for (int mt = 0; mt < 2; mt++) {
            float c[4] = {0.f, 0.f, 0.f, 0.f};
            #pragma unroll
            for (int ks = 0; ks < 4; ks++) {
                mma_tf32(c, qa_hi[mt][ks], bh[ks]);
                mma_tf32(c, qa_hi[mt][ks], bl[ks]);
                mma_tf32(c, qa_lo[mt][ks], bh[ks]);
            }
            int row = mt*16 + (lane >> 2);
            int col = kt*64 + w*8 + 2*(lane & 3);
            *(float2*)&S[row*SPITCH + col]     = make_float2(c[0], c[1]);
            *(float2*)&S[(row+8)*SPITCH + col] = make_float2(c[2], c[3]);
        }
    }
    __syncthreads();

    // ---- prefetch V stage 0 ----
    float4 vreg[4];
    #pragma unroll
    for (int i = 0; i < 4; i++) {
        int f = 256*i + tid;
        int key = f >> 4, c4 = f & 15;
        vreg[i] = *(const float4*)&Vc[((size_t)key * BSZ + b) * DEXP + h*HDIM + c4*4];
    }

    // ---- phase 2: softmax + attn write ----
    {
        for (int rr = 0; rr < 4; rr++) {
            int r = w + 8*rr;
            float* row = S + r*SPITCH;
            float m = -1e30f;
            for (int k = lane; k < 1024; k += 32) m = fmaxf(m, row[k]);
            #pragma unroll
            for (int o = 16; o; o >>= 1) m = fmaxf(m, __shfl_xor_sync(0xffffffffu, m, o));
            float s = 0.f;
            for (int k = lane; k < 1024; k += 32) {
                float e = __expf(row[k] - m);
                row[k] = e; s += e;
            }
            #pragma unroll
            for (int o = 16; o; o >>= 1) s += __shfl_xor_sync(0xffffffffu, s, o);
            float inv = 1.0f / s;
            float* g = attn_out ? attn_out + (((size_t)(b*NHEAD + h) * LL + (r0 + r)) * LL) : nullptr;
            for (int k = lane; k < 1024; k += 32) {
                float p = row[k] * inv;
                row[k] = p;
                if (g) g[k] = p;
            }
        }
    }

    // ---- phase 3: AV + U-gate ----
    float cav[2][4] = {};
    for (int vt = 0; vt < 16; vt++) {
        #pragma unroll
        for (int i = 0; i < 4; i++) {
            int f = 256*i + tid;
            int key = f >> 4, c4 = f & 15;
            *(float4*)&buf[key*VPITCH + c4*4] = vreg[i];
        }
        __syncthreads();
        if (vt < 15) {
            int base = (vt + 1) * 64;
            #pragma unroll
            for (int i = 0; i < 4; i++) {
                int f = 256*i + tid;
                int key = base + (f >> 4), c4 = f & 15;
                vreg[i] = *(const float4*)&Vc[((size_t)key * BSZ + b) * DEXP + h*HDIM + c4*4];
            }
        }
        #pragma unroll
        for (int ks = 0; ks < 8; ks++) {
            int kk = ks*8 + (lane & 3);
            int nn = w*8 + (lane >> 2);
            uint32_t bfh[2], bfl[2];
            tf32_split(buf[kk*VPITCH + nn],     bfh[0], bfl[0]);
            tf32_split(buf[(kk+4)*VPITCH + nn], bfh[1], bfl[1]);
            #pragma unroll
            for (int mt = 0; mt < 2; mt++) {
                int r = mt*16 + (lane >> 2);
                int d = vt*64 + ks*8 + (lane & 3);
                uint32_t ah[4], al[4];
                tf32_split(S[r*SPITCH + d],         ah[0], al[0]);
                tf32_split(S[(r+8)*SPITCH + d],     ah[1], al[1]);
                tf32_split(S[r*SPITCH + d + 4],     ah[2], al[2]);
                tf32_split(S[(r+8)*SPITCH + d + 4], ah[3], al[3]);
                mma_tf32(cav[mt], ah, bfh);
                mma_tf32(cav[mt], ah, bfl);
                mma_tf32(cav[mt], al, bfh);
            }
        }
        __syncthreads();
    }

    // ---- epilogue: U-gate and write ----
    #pragma unroll
    for (int mt = 0; mt < 2; mt++) {
        int row = mt*16 + (lane >> 2);
        int col = h*HDIM + w*8 + 2*(lane & 3);
        {
            size_t base = ((size_t)(r0 + row) * BSZ + b) * DEXP;
            float2 u = *(const float2*)&Uc[base + col];
            *(float2*)&Gout[base + col] = make_float2(cav[mt][0]*u.x, cav[mt][1]*u.y);
        }
        {
            size_t base = ((size_t)(r0 + row + 8) * BSZ + b) * DEXP;
            float2 u = *(const float2*)&Uc[base + col];
            *(float2*)&Gout[base + col] = make_float2(cav[mt][2]*u.x, cav[mt][3]*u.y);
        }
    }
}

// ---------------- depthwise 5x5 conv ----------------
__global__ __launch_bounds__(256) void dwconv_kernel(
    const float* __restrict__ X, const float* __restrict__ Wc, float* __restrict__ Y)
{
    extern __shared__ float sm[];
    float* xs = sm;             // [1024][33]
    float* ws = sm + 1024*33;   // [32][25]
    const int c0 = blockIdx.x * 32, b = blockIdx.y;
    const int tid = threadIdx.x;

    for (int idx = tid; idx < 1024*32; idx += 256) {
        int t = idx >> 5, c = idx & 31;
        xs[t*33 + c] = X[((size_t)t * BSZ + b) * DEXP + c0 + c];
    }
    for (int idx = tid; idx < 32*25; idx += 256) {
        int c = idx / 25, t = idx % 25;
        ws[c*25 + t] = Wc[(size_t)(c0 + c) * 25 + t];
    }
    __syncthreads();

    const int c = tid & 31, pr = tid >> 5;
    for (int s = 0; s < 128; s++) {
        int pos = pr + 8*s;
        int i = pos >> 5, j = pos & 31;
        float acc = 0.f;
        #pragma unroll
        for (int di = 0; di < 5; di++) {
            int ii = i + di - 2;
            if (ii < 0 || ii >= 32) continue;
            #pragma unroll
            for (int dj = 0; dj < 5; dj++) {
                int jj = j + dj - 2;
                if (jj < 0 || jj >= 32) continue;
                acc += xs[(ii*32 + jj)*33 + c] * ws[c*25 + di*5 + dj];
            }
        }
        Y[((size_t)pos * BSZ + b) * DEXP + c0 + c] = acc;
    }
}

// ---------------- launch ----------------
extern "C" void kernel_launch(void* const* d_in, const int* in_sizes, int n_in,
                              void* d_out, int out_size)
{
    const float* Q   = (const float*)d_in[0];
    const float* V   = (const float*)d_in[2];
    const float* U   = (const float*)d_in[3];
    const float* Wqk = (const float*)d_in[4];
    const float* bqk = (const float*)d_in[5];
    const float* Wv1 = (const float*)d_in[6];
    const float* bv1 = (const float*)d_in[7];
    const float* Wv2 = (const float*)d_in[8];
    const float* bv2 = (const float*)d_in[9];
    const float* Wu1 = (const float*)d_in[10];
    const float* bu1 = (const float*)d_in[11];
    const float* Wu2 = (const float*)d_in[12];
    const float* bu2 = (const float*)d_in[13];
    const float* Wcv = (const float*)d_in[14];
    const float* Wp  = (const float*)d_in[15];
    const float* bp  = (const float*)d_in[16];

    float* out  = (float*)d_out;
    float* attn = (out_size > MROWS*DQK) ? out + (size_t)MROWS*DQK : nullptr;

    float *Qp, *Vc, *Uc, *G, *Y;
    cudaGetSymbolAddress((void**)&Qp, g_Qp);
    cudaGetSymbolAddress((void**)&Vc, g_Vc);
    cudaGetSymbolAddress((void**)&Uc, g_Uc);
    cudaGetSymbolAddress((void**)&G,  g_G);
    cudaGetSymbolAddress((void**)&Y,  g_Y);

    const size_t ATTN_SMEM = (size_t)(32*SPITCH + 64*VPITCH + 32*33) * sizeof(float); // ~154 KB
    const size_t CONV_SMEM = (size_t)(1024*33 + 32*25) * sizeof(float);               // ~138 KB
    cudaFuncSetAttribute(attn_kernel,   cudaFuncAttributeMaxDynamicSharedMemorySize, (int)ATTN_SMEM);
    cudaFuncSetAttribute(dwconv_kernel, cudaFuncAttributeMaxDynamicSharedMemorySize, (int)CONV_SMEM);

    // 1) Qp = Q @ Wqk + bqk
    {
        dim3 grid(DQK/64, MROWS/64);
        gemm_bias_kernel<<<grid, 256>>>(Q, Wqk, bqk, Qp, MROWS, DQK, DQK);
    }
    // 2) Vc, Uc gated projections
    {
        dim3 grid(16, MROWS/64);
        gated_proj_kernel<<<grid, 256>>>(V, Wv1, bv1, Wv2, bv2, Vc);
        gated_proj_kernel<<<grid, 256>>>(U, Wu1, bu1, Wu2, bu2, Uc);
    }
    // 3) attention (+ attn output + U-gate)
    {
        dim3 grid(LL/32, NHEAD, BSZ);
        attn_kernel<<<grid, 256, ATTN_SMEM>>>(Qp, Vc, Uc, attn, G);
    }
    // 4) depthwise conv
    {
        dim3 grid(16, BSZ);
        dwconv_kernel<<<grid, 256, CONV_SMEM>>>(G, Wcv, Y);
    }
    // 5) outputs = Y @ Wp + bp
    {
        dim3 grid(DQK/64, MROWS/64);
        gemm_bias_kernel<<<grid, 256>>>(Y, Wp, bp, out, MROWS, DQK, DEXP);
    }
}

// round 5
// speedup vs baseline: 1.8078x; 1.0864x over previous
#include <cuda_runtime.h>
#include <cuda_bf16.h>
#include <math.h>
#include <stdint.h>

#define LL    1024
#define BSZ   8
#define DQK   256
#define DEXP  512
#define NHEAD 8
#define HDIM  64
#define DATT  32
#define MROWS (LL*BSZ)   // 8192
#define HALF_OUT 256
#define SPITCH 1028      // S row pitch (floats/u32), even -> 8B-aligned pair loads
#define VPITCH 72        // V-tile pitch: float4-aligned

// ---------------- scratch ----------------
__device__ __align__(256) float g_Qp[MROWS*DQK];
__device__ __align__(256) float g_Vc[MROWS*DEXP];
__device__ __align__(256) float g_Uc[MROWS*DEXP];
__device__ __align__(256) float g_G [MROWS*DEXP];
__device__ __align__(256) float g_Y [MROWS*DEXP];

// ---------------- bf16 split helpers ----------------
// Pack adjacent-k pair (x0 low half, x1 high half) into hi and lo bf16x2 regs.
__device__ __forceinline__ void bf16_split_pair(float x0, float x1, uint32_t& hi, uint32_t& lo) {
    uint32_t h;
    asm("cvt.rn.bf16x2.f32 %0, %1, %2;" : "=r"(h) : "f"(x1), "f"(x0));
    float h0 = __uint_as_float(h << 16);
    float h1 = __uint_as_float(h & 0xffff0000u);
    uint32_t l;
    asm("cvt.rn.bf16x2.f32 %0, %1, %2;" : "=r"(l) : "f"(x1 - h1), "f"(x0 - h0));
    hi = h; lo = l;
}

// One element -> packed u32: hi bf16 in low 16, lo bf16 in high 16.
__device__ __forceinline__ uint32_t bf16_split_elem(float x) {
    __nv_bfloat16 hb = __float2bfloat16_rn(x);
    float hf = __bfloat162float(hb);
    __nv_bfloat16 lb = __float2bfloat16_rn(x - hf);
    return ((uint32_t)__bfloat16_as_ushort(lb) << 16) | (uint32_t)__bfloat16_as_ushort(hb);
}

__device__ __forceinline__ void mma_bf16(float* c, const uint32_t* a, const uint32_t* b) {
    asm volatile(
        "mma.sync.aligned.m16n8k16.row.col.f32.bf16.bf16.f32 "
        "{%0,%1,%2,%3},{%4,%5,%6,%7},{%8,%9},{%0,%1,%2,%3};"
        : "+f"(c[0]), "+f"(c[1]), "+f"(c[2]), "+f"(c[3])
        : "r"(a[0]), "r"(a[1]), "r"(a[2]), "r"(a[3]), "r"(b[0]), "r"(b[1]));
}

// ---------------- generic tiled GEMM + bias ----------------
__global__ __launch_bounds__(256) void gemm_bias_kernel(
    const float* __restrict__ A, const float* __restrict__ B,
    const float* __restrict__ bias, float* __restrict__ C,
    int M, int N, int K)
{
    __shared__ float As[16][65];
    __shared__ float Bs[16][64];
    const int m0 = blockIdx.y * 64, n0 = blockIdx.x * 64;
    const int tid = threadIdx.x;
    const int tx = tid & 15, ty = tid >> 4;
    float acc[4][4] = {};

    for (int k0 = 0; k0 < K; k0 += 16) {
        #pragma unroll
        for (int idx = tid; idx < 64*16; idx += 256) {
            int r = idx >> 4, kk = idx & 15;
            As[kk][r] = A[(size_t)(m0 + r) * K + k0 + kk];
        }
        #pragma unroll
        for (int idx = tid; idx < 16*64; idx += 256) {
            int kk = idx >> 6, c = idx & 63;
            Bs[kk][c] = B[(size_t)(k0 + kk) * N + n0 + c];
        }
        __syncthreads();
        #pragma unroll
        for (int kk = 0; kk < 16; kk++) {
            float a[4], b[4];
            #pragma unroll
            for (int i = 0; i < 4; i++) a[i] = As[kk][ty + 16*i];
            #pragma unroll
            for (int j = 0; j < 4; j++) b[j] = Bs[kk][tx + 16*j];
            #pragma unroll
            for (int i = 0; i < 4; i++)
                #pragma unroll
                for (int j = 0; j < 4; j++)
                    acc[i][j] += a[i] * b[j];
        }
        __syncthreads();
    }
    #pragma unroll
    for (int i = 0; i < 4; i++) {
        int r = m0 + ty + 16*i;
        #pragma unroll
        for (int j = 0; j < 4; j++) {
            int c = n0 + tx + 16*j;
            C[(size_t)r * N + c] = acc[i][j] + bias[c];
        }
    }
}

// ---------------- gated half-projection + SiLU ----------------
__global__ __launch_bounds__(256) void gated_proj_kernel(
    const float* __restrict__ X,
    const float* __restrict__ W1, const float* __restrict__ b1,
    const float* __restrict__ W2, const float* __restrict__ b2,
    float* __restrict__ Yout)
{
    __shared__ float As[16][65];
    __shared__ float Bs[16][32];
    const int c0   = blockIdx.x * 32;
    const int head = c0 >> 6;
    const int is2  = (c0 >> 5) & 1;
    const float* W  = is2 ? W2 : W1;
    const float* bb = is2 ? b2 : b1;
    const int wc0 = head * 32;
    const float* Ain = X + (is2 ? 128 : 0);
    const int m0 = blockIdx.y * 64;
    const int tid = threadIdx.x;
    const int tx = tid & 31, ty = tid >> 5;
    float acc[8] = {};

    for (int k0 = 0; k0 < 128; k0 += 16) {
        #pragma unroll
        for (int idx = tid; idx < 64*16; idx += 256) {
            int r = idx >> 4, kk = idx & 15;
            As[kk][r] = Ain[(size_t)(m0 + r) * 256 + k0 + kk];
        }
        #pragma unroll
        for (int idx = tid; idx < 16*32; idx += 256) {
            int kk = idx >> 5, c = idx & 31;
            Bs[kk][c] = W[(size_t)(k0 + kk) * HALF_OUT + wc0 + c];
        }
        __syncthreads();
        #pragma unroll
        for (int kk = 0; kk < 16; kk++) {
            float bv = Bs[kk][tx];
            #pragma unroll
            for (int i = 0; i < 8; i++)
                acc[i] += As[kk][ty + 8*i] * bv;
        }
        __syncthreads();
    }
    float bias = bb[wc0 + tx];
    #pragma unroll
    for (int i = 0; i < 8; i++) {
        int r = m0 + ty + 8*i;
        float v = acc[i] + bias;
        float y = v / (1.0f + __expf(-v));
        Yout[(size_t)r * DEXP + c0 + tx] = y;
    }
}

// ---------------- fused attention (bf16x3 tensor-core) ----------------
// grid: (32 row-tiles, NHEAD, BSZ), 256 threads = 8 warps.
// smem: S[32][SPITCH] | buf[64*VPITCH] | Qbuf[32][33]
__global__ __launch_bounds__(256) void attn_kernel(
    const float* __restrict__ Qp, const float* __restrict__ Vc,
    const float* __restrict__ Uc, float* __restrict__ attn_out,
    float* __restrict__ Gout)
{
    extern __shared__ float sm[];
    float* S     = sm;                  // 32 * SPITCH (fp32 scores, then packed bf16 pairs)
    uint32_t* Su = (uint32_t*)sm;
    float* buf   = S + 32*SPITCH;       // 64*VPITCH
    float* Qbuf  = buf + 64*VPITCH;     // 32*33

    const int r0 = blockIdx.x * 32;
    const int h  = blockIdx.y, b = blockIdx.z;
    const int tid  = threadIdx.x;
    const int lane = tid & 31;
    const int w    = tid >> 5;
    const int g    = lane >> 2;         // group id (row / n)
    const int t    = lane & 3;          // thread-in-group (k)
    const float scale = 0.17677669529663687f;   // 1/sqrt(32)

    // ---- load Q tile (scaled); prefetch K stage 0 ----
    #pragma unroll
    for (int i = 0; i < 4; i++) {
        int idx = 256*i + tid;
        int r = idx >> 5, d = idx & 31;
        Qbuf[r*33 + d] = Qp[((size_t)(r0 + r) * BSZ + b) * DQK + h*DATT + d] * scale;
    }
    float kreg[8];
    #pragma unroll
    for (int i = 0; i < 8; i++) {
        int idx = 256*i + tid;
        int key = idx >> 5, d = idx & 31;
        kreg[i] = Qp[((size_t)key * BSZ + b) * DQK + h*DATT + d];
    }
    __syncthreads();

    // ---- Q fragments: m16n8k16, 2 k-steps over DATT=32, hi/lo bf16 ----
    uint32_t qa_hi[2][2][4], qa_lo[2][2][4];
    #pragma unroll
    for (int mt = 0; mt < 2; mt++) {
        int r = mt*16 + g;
        #pragma unroll
        for (int ks = 0; ks < 2; ks++) {
            int d = ks*16 + 2*t;
            bf16_split_pair(Qbuf[r*33 + d],         Qbuf[r*33 + d + 1],       qa_hi[mt][ks][0], qa_lo[mt][ks][0]);
            bf16_split_pair(Qbuf[(r+8)*33 + d],     Qbuf[(r+8)*33 + d + 1],   qa_hi[mt][ks][1], qa_lo[mt][ks][1]);
            bf16_split_pair(Qbuf[r*33 + d + 8],     Qbuf[r*33 + d + 9],       qa_hi[mt][ks][2], qa_lo[mt][ks][2]);
            bf16_split_pair(Qbuf[(r+8)*33 + d + 8], Qbuf[(r+8)*33 + d + 9],   qa_hi[mt][ks][3], qa_lo[mt][ks][3]);
        }
    }

    // ---- phase 1: scores S = Qs @ K^T ----
    for (int kt = 0; kt < 16; kt++) {
        #pragma unroll
        for (int i = 0; i < 8; i++) {
            int idx = 256*i + tid;
            buf[(idx >> 5)*33 + (idx & 31)] = kreg[i];
        }
        __syncthreads();
        if (kt < 15) {
            int base = (kt + 1) * 64;
            #pragma unroll
            for (int i = 0; i < 8; i++) {
                int idx = 256*i + tid;
                int key = base + (idx >> 5), d = idx & 31;
                kreg[i] = Qp[((size_t)key * BSZ + b) * DQK + h*DATT + d];
            }
        }
        // B fragments: keys n = w*8 + g
        uint32_t bh[2][2], bl[2][2];
        {
            int key = w*8 + g;
            #pragma unroll
            for (int ks = 0; ks < 2; ks++) {
                int d = ks*16 + 2*t;
                bf16_split_pair(buf[key*33 + d],     buf[key*33 + d + 1], bh[ks][0], bl[ks][0]);
                bf16_split_pair(buf[key*33 + d + 8], buf[key*33 + d + 9], bh[ks][1], bl[ks][1]);
            }
        }
        __syncthreads();
        #pragma unroll
        for (int mt = 0; mt < 2; mt++) {
            float c[4] = {0.f, 0.f, 0.f, 0.f};
            #pragma unroll
            for (int ks = 0; ks < 2; ks++) {
                mma_bf16(c, qa_hi[mt][ks], bh[ks]);
                mma_bf16(c, qa_hi[mt][ks], bl[ks]);
                mma_bf16(c, qa_lo[mt][ks], bh[ks]);
            }
            int row = mt*16 + g;
            int col = kt*64 + w*8 + 2*t;
            *(float2*)&S[row*SPITCH + col]     = make_float2(c[0], c[1]);
            *(float2*)&S[(row+8)*SPITCH + col] = make_float2(c[2], c[3]);
        }
    }
    __syncthreads();

    // ---- prefetch V stage 0 ----
    float4 vreg[4];
    #pragma unroll
    for (int i = 0; i < 4; i++) {
        int f = 256*i + tid;
        int key = f >> 4, c4 = f & 15;
        vreg[i] = *(const float4*)&Vc[((size_t)key * BSZ + b) * DEXP + h*HDIM + c4*4];
    }

    // ---- phase 2: softmax + attn write; store packed bf16(hi,lo) in place ----
    {
        for (int rr = 0; rr < 4; rr++) {
            int r = w + 8*rr;
            float* row = S + r*SPITCH;
            uint32_t* urow = Su + r*SPITCH;
            float m = -1e30f;
            for (int k = lane; k < 1024; k += 32) m = fmaxf(m, row[k]);
            #pragma unroll
            for (int o = 16; o; o >>= 1) m = fmaxf(m, __shfl_xor_sync(0xffffffffu, m, o));
            float s = 0.f;
            for (int k = lane; k < 1024; k += 32) {
                float e = __expf(row[k] - m);
                row[k] = e; s += e;
            }
            #pragma unroll
            for (int o = 16; o; o >>= 1) s += __shfl_xor_sync(0xffffffffu, s, o);
            float inv = 1.0f / s;
            float* gp = attn_out ? attn_out + (((size_t)(b*NHEAD + h) * LL + (r0 + r)) * LL) : nullptr;
            for (int k = lane; k < 1024; k += 32) {
                float p = row[k] * inv;
                if (gp) gp[k] = p;
                urow[k] = bf16_split_elem(p);
            }
        }
    }

    // ---- phase 3: AV (bf16x3) + U-gate ----
    float cav[2][4] = {};
    for (int vt = 0; vt < 16; vt++) {
        #pragma unroll
        for (int i = 0; i < 4; i++) {
            int f = 256*i + tid;
            int key = f >> 4, c4 = f & 15;
            *(float4*)&buf[key*VPITCH + c4*4] = vreg[i];
        }
        __syncthreads();
        if (vt < 15) {
            int base = (vt + 1) * 64;
            #pragma unroll
            for (int i = 0; i < 4; i++) {
                int f = 256*i + tid;
                int key = base + (f >> 4), c4 = f & 15;
                vreg[i] = *(const float4*)&Vc[((size_t)key * BSZ + b) * DEXP + h*HDIM + c4*4];
            }
        }
        const int nn = w*8 + g;
        #pragma unroll
        for (int ks = 0; ks < 4; ks++) {     // 4 x k16 over 64 keys
            int kk = ks*16 + 2*t;
            uint32_t bfh[2], bfl[2];
            bf16_split_pair(buf[kk*VPITCH + nn],     buf[(kk+1)*VPITCH + nn], bfh[0], bfl[0]);
            bf16_split_pair(buf[(kk+8)*VPITCH + nn], buf[(kk+9)*VPITCH + nn], bfh[1], bfl[1]);
            #pragma unroll
            for (int mt = 0; mt < 2; mt++) {
                int r = mt*16 + g;
                int d = vt*64 + ks*16 + 2*t;
                uint2 p0 = *(const uint2*)&Su[r*SPITCH + d];
                uint2 p1 = *(const uint2*)&Su[(r+8)*SPITCH + d];
                uint2 p2 = *(const uint2*)&Su[r*SPITCH + d + 8];
                uint2 p3 = *(const uint2*)&Su[(r+8)*SPITCH + d + 8];
                uint32_t ah[4], al[4];
                ah[0] = __byte_perm(p0.x, p0.y, 0x5410); al[0] = __byte_perm(p0.x, p0.y, 0x7632);
                ah[1] = __byte_perm(p1.x, p1.y, 0x5410); al[1] = __byte_perm(p1.x, p1.y, 0x7632);
                ah[2] = __byte_perm(p2.x, p2.y, 0x5410); al[2] = __byte_perm(p2.x, p2.y, 0x7632);
                ah[3] = __byte_perm(p3.x, p3.y, 0x5410); al[3] = __byte_perm(p3.x, p3.y, 0x7632);
                mma_bf16(cav[mt], ah, bfh);
                mma_bf16(cav[mt], ah, bfl);
                mma_bf16(cav[mt], al, bfh);
            }
        }
        __syncthreads();
    }

    // ---- epilogue: U-gate and write ----
    #pragma unroll
    for (int mt = 0; mt < 2; mt++) {
        int row = mt*16 + g;
        int col = h*HDIM + w*8 + 2*t;
        {
            size_t base = ((size_t)(r0 + row) * BSZ + b) * DEXP;
            float2 u = *(const float2*)&Uc[base + col];
            *(float2*)&Gout[base + col] = make_float2(cav[mt][0]*u.x, cav[mt][1]*u.y);
        }
        {
            size_t base = ((size_t)(r0 + row + 8) * BSZ + b) * DEXP;
            float2 u = *(const float2*)&Uc[base + col];
            *(float2*)&Gout[base + col] = make_float2(cav[mt][2]*u.x, cav[mt][3]*u.y);
        }
    }
}

// ---------------- depthwise 5x5 conv ----------------
__global__ __launch_bounds__(256) void dwconv_kernel(
    const float* __restrict__ X, const float* __restrict__ Wc, float* __restrict__ Y)
{
    extern __shared__ float sm[];
    float* xs = sm;             // [1024][33]
    float* ws = sm + 1024*33;   // [32][25]
    const int c0 = blockIdx.x * 32, b = blockIdx.y;
    const int tid = threadIdx.x;

    for (int idx = tid; idx < 1024*32; idx += 256) {
        int t = idx >> 5, c = idx & 31;
        xs[t*33 + c] = X[((size_t)t * BSZ + b) * DEXP + c0 + c];
    }
    for (int idx = tid; idx < 32*25; idx += 256) {
        int c = idx / 25, t = idx % 25;
        ws[c*25 + t] = Wc[(size_t)(c0 + c) * 25 + t];
    }
    __syncthreads();

    const int c = tid & 31, pr = tid >> 5;
    for (int s = 0; s < 128; s++) {
        int pos = pr + 8*s;
        int i = pos >> 5, j = pos & 31;
        float acc = 0.f;
        #pragma unroll
        for (int di = 0; di < 5; di++) {
            int ii = i + di - 2;
            if (ii < 0 || ii >= 32) continue;
            #pragma unroll
            for (int dj = 0; dj < 5; dj++) {
                int jj = j + dj - 2;
                if (jj < 0 || jj >= 32) continue;
                acc += xs[(ii*32 + jj)*33 + c] * ws[c*25 + di*5 + dj];
            }
        }
        Y[((size_t)pos * BSZ + b) * DEXP + c0 + c] = acc;
    }
}

// ---------------- launch ----------------
extern "C" void kernel_launch(void* const* d_in, const int* in_sizes, int n_in,
                              void* d_out, int out_size)
{
    const float* Q   = (const float*)d_in[0];
    const float* V   = (const float*)d_in[2];
    const float* U   = (const float*)d_in[3];
    const float* Wqk = (const float*)d_in[4];
    const float* bqk = (const float*)d_in[5];
    const float* Wv1 = (const float*)d_in[6];
    const float* bv1 = (const float*)d_in[7];
    const float* Wv2 = (const float*)d_in[8];
    const float* bv2 = (const float*)d_in[9];
    const float* Wu1 = (const float*)d_in[10];
    const float* bu1 = (const float*)d_in[11];
    const float* Wu2 = (const float*)d_in[12];
    const float* bu2 = (const float*)d_in[13];
    const float* Wcv = (const float*)d_in[14];
    const float* Wp  = (const float*)d_in[15];
    const float* bp  = (const float*)d_in[16];

    float* out  = (float*)d_out;
    float* attn = (out_size > MROWS*DQK) ? out + (size_t)MROWS*DQK : nullptr;

    float *Qp, *Vc, *Uc, *G, *Y;
    cudaGetSymbolAddress((void**)&Qp, g_Qp);
    cudaGetSymbolAddress((void**)&Vc, g_Vc);
    cudaGetSymbolAddress((void**)&Uc, g_Uc);
    cudaGetSymbolAddress((void**)&G,  g_G);
    cudaGetSymbolAddress((void**)&Y,  g_Y);

    const size_t ATTN_SMEM = (size_t)(32*SPITCH + 64*VPITCH + 32*33) * sizeof(float);
    const size_t CONV_SMEM = (size_t)(1024*33 + 32*25) * sizeof(float);
    cudaFuncSetAttribute(attn_kernel,   cudaFuncAttributeMaxDynamicSharedMemorySize, (int)ATTN_SMEM);
    cudaFuncSetAttribute(dwconv_kernel, cudaFuncAttributeMaxDynamicSharedMemorySize, (int)CONV_SMEM);

    {
        dim3 grid(DQK/64, MROWS/64);
        gemm_bias_kernel<<<grid, 256>>>(Q, Wqk, bqk, Qp, MROWS, DQK, DQK);
    }
    {
        dim3 grid(16, MROWS/64);
        gated_proj_kernel<<<grid, 256>>>(V, Wv1, bv1, Wv2, bv2, Vc);
        gated_proj_kernel<<<grid, 256>>>(U, Wu1, bu1, Wu2, bu2, Uc);
    }
    {
        dim3 grid(LL/32, NHEAD, BSZ);
        attn_kernel<<<grid, 256, ATTN_SMEM>>>(Qp, Vc, Uc, attn, G);
    }
    {
        dim3 grid(16, BSZ);
        dwconv_kernel<<<grid, 256, CONV_SMEM>>>(G, Wcv, Y);
    }
    {
        dim3 grid(DQK/64, MROWS/64);
        gemm_bias_kernel<<<grid, 256>>>(Y, Wp, bp, out, MROWS, DQK, DEXP);
    }
}

// round 6
// speedup vs baseline: 1.8923x; 1.0467x over previous
#include <cuda_runtime.h>
#include <cuda_bf16.h>
#include <math.h>
#include <stdint.h>

#define LL    1024
#define BSZ   8
#define DQK   256
#define DEXP  512
#define NHEAD 8
#define HDIM  64
#define DATT  32
#define MROWS (LL*BSZ)   // 8192
#define HALF_OUT 256
#define SPITCH 1032      // S pitch (u32/f32). 1032 = 8 mod 32 -> conflict-free LDS.64
#define KPITCH 40        // K-tile pitch (u32)
#define QPITCH 40        // Q-tile pitch (u32)
#define VPITCH 68        // V-tile pitch (u32), uint4-aligned, conflict-free frag loads

// ---------------- scratch ----------------
__device__ __align__(256) uint32_t g_Qps[MROWS*DQK];   // packed bf16(hi,lo) Qp
__device__ __align__(256) uint32_t g_Vps[MROWS*DEXP];  // packed bf16(hi,lo) Vc
__device__ __align__(256) float    g_Uc [MROWS*DEXP];  // fp32 Uc (gating)
__device__ __align__(256) float    g_G  [MROWS*DEXP];
__device__ __align__(256) float    g_Y  [MROWS*DEXP];

// ---------------- helpers ----------------
// One element -> packed u32: hi bf16 in low 16, lo bf16 in high 16.
__device__ __forceinline__ uint32_t bf16_split_elem(float x) {
    __nv_bfloat16 hb = __float2bfloat16_rn(x);
    float hf = __bfloat162float(hb);
    __nv_bfloat16 lb = __float2bfloat16_rn(x - hf);
    return ((uint32_t)__bfloat16_as_ushort(lb) << 16) | (uint32_t)__bfloat16_as_ushort(hb);
}

__device__ __forceinline__ void mma_bf16(float* c, const uint32_t* a, const uint32_t* b) {
    asm volatile(
        "mma.sync.aligned.m16n8k16.row.col.f32.bf16.bf16.f32 "
        "{%0,%1,%2,%3},{%4,%5,%6,%7},{%8,%9},{%0,%1,%2,%3};"
        : "+f"(c[0]), "+f"(c[1]), "+f"(c[2]), "+f"(c[3])
        : "r"(a[0]), "r"(a[1]), "r"(a[2]), "r"(a[3]), "r"(b[0]), "r"(b[1]));
}

#define PERM_HI(p0, p1) __byte_perm((p0), (p1), 0x5410)
#define PERM_LO(p0, p1) __byte_perm((p0), (p1), 0x7632)

// ---------------- generic tiled GEMM + bias; mode0: fp32 out, mode1: packed u32 out ----------------
__global__ __launch_bounds__(256) void gemm_bias_kernel(
    const float* __restrict__ A, const float* __restrict__ B,
    const float* __restrict__ bias, void* __restrict__ Cv,
    int M, int N, int K, int mode)
{
    __shared__ float As[16][65];
    __shared__ float Bs[16][64];
    const int m0 = blockIdx.y * 64, n0 = blockIdx.x * 64;
    const int tid = threadIdx.x;
    const int tx = tid & 15, ty = tid >> 4;
    float acc[4][4] = {};

    for (int k0 = 0; k0 < K; k0 += 16) {
        #pragma unroll
        for (int idx = tid; idx < 64*16; idx += 256) {
            int r = idx >> 4, kk = idx & 15;
            As[kk][r] = A[(size_t)(m0 + r) * K + k0 + kk];
        }
        #pragma unroll
        for (int idx = tid; idx < 16*64; idx += 256) {
            int kk = idx >> 6, c = idx & 63;
            Bs[kk][c] = B[(size_t)(k0 + kk) * N + n0 + c];
        }
        __syncthreads();
        #pragma unroll
        for (int kk = 0; kk < 16; kk++) {
            float a[4], b[4];
            #pragma unroll
            for (int i = 0; i < 4; i++) a[i] = As[kk][ty + 16*i];
            #pragma unroll
            for (int j = 0; j < 4; j++) b[j] = Bs[kk][tx + 16*j];
            #pragma unroll
            for (int i = 0; i < 4; i++)
                #pragma unroll
                for (int j = 0; j < 4; j++)
                    acc[i][j] += a[i] * b[j];
        }
        __syncthreads();
    }
    #pragma unroll
    for (int i = 0; i < 4; i++) {
        int r = m0 + ty + 16*i;
        #pragma unroll
        for (int j = 0; j < 4; j++) {
            int c = n0 + tx + 16*j;
            float v = acc[i][j] + bias[c];
            if (mode == 0) ((float*)Cv)[(size_t)r * N + c] = v;
            else           ((uint32_t*)Cv)[(size_t)r * N + c] = bf16_split_elem(v);
        }
    }
}

// ---------------- gated half-projection + SiLU; packed=1 -> u32 out ----------------
__global__ __launch_bounds__(256) void gated_proj_kernel(
    const float* __restrict__ X,
    const float* __restrict__ W1, const float* __restrict__ b1,
    const float* __restrict__ W2, const float* __restrict__ b2,
    void* __restrict__ Yv, int packed)
{
    __shared__ float As[16][65];
    __shared__ float Bs[16][32];
    const int c0   = blockIdx.x * 32;
    const int head = c0 >> 6;
    const int is2  = (c0 >> 5) & 1;
    const float* W  = is2 ? W2 : W1;
    const float* bb = is2 ? b2 : b1;
    const int wc0 = head * 32;
    const float* Ain = X + (is2 ? 128 : 0);
    const int m0 = blockIdx.y * 64;
    const int tid = threadIdx.x;
    const int tx = tid & 31, ty = tid >> 5;
    float acc[8] = {};

    for (int k0 = 0; k0 < 128; k0 += 16) {
        #pragma unroll
        for (int idx = tid; idx < 64*16; idx += 256) {
            int r = idx >> 4, kk = idx & 15;
            As[kk][r] = Ain[(size_t)(m0 + r) * 256 + k0 + kk];
        }
        #pragma unroll
        for (int idx = tid; idx < 16*32; idx += 256) {
            int kk = idx >> 5, c = idx & 31;
            Bs[kk][c] = W[(size_t)(k0 + kk) * HALF_OUT + wc0 + c];
        }
        __syncthreads();
        #pragma unroll
        for (int kk = 0; kk < 16; kk++) {
            float bv = Bs[kk][tx];
            #pragma unroll
            for (int i = 0; i < 8; i++)
                acc[i] += As[kk][ty + 8*i] * bv;
        }
        __syncthreads();
    }
    float bias = bb[wc0 + tx];
    #pragma unroll
    for (int i = 0; i < 8; i++) {
        int r = m0 + ty + 8*i;
        float v = acc[i] + bias;
        float y = v / (1.0f + __expf(-v));
        if (packed) ((uint32_t*)Yv)[(size_t)r * DEXP + c0 + tx] = bf16_split_elem(y);
        else        ((float*)Yv)[(size_t)r * DEXP + c0 + tx] = y;
    }
}

// ---------------- fused attention (bf16x3, ks-split AV) ----------------
// grid: (32 row-tiles, NHEAD, BSZ), 256 threads = 8 warps.
__global__ __launch_bounds__(256) void attn_kernel(
    const uint32_t* __restrict__ Qps, const uint32_t* __restrict__ Vps,
    const float* __restrict__ Uc, float* __restrict__ attn_out,
    float* __restrict__ Gout)
{
    extern __shared__ float sm[];
    float*    Sf  = sm;                            // 32 * SPITCH (fp32 scores -> packed P -> R overlay)
    uint32_t* Su  = (uint32_t*)sm;
    uint32_t* buf = (uint32_t*)(sm + 32*SPITCH);   // 64*VPITCH (V) / 64*KPITCH (K)
    uint32_t* Qb  = buf + 64*VPITCH;               // 32*QPITCH
    float*    R   = sm;                            // reduction overlay: [4][32][64]

    const int r0 = blockIdx.x * 32;
    const int h  = blockIdx.y, b = blockIdx.z;
    const int tid  = threadIdx.x;
    const int lane = tid & 31;
    const int w    = tid >> 5;
    const int g    = lane >> 2;
    const int t    = lane & 3;
    const float scale = 0.17677669529663687f;   // 1/sqrt(32)

    // ---- load Q tile (packed u32); prefetch K stage 0 ----
    #pragma unroll
    for (int i = 0; i < 4; i++) {
        int idx = 256*i + tid;
        int r = idx >> 5, d = idx & 31;
        Qb[r*QPITCH + d] = Qps[((size_t)(r0 + r) * BSZ + b) * DQK + h*DATT + d];
    }
    uint32_t kreg[8];
    #pragma unroll
    for (int i = 0; i < 8; i++) {
        int idx = 256*i + tid;
        int key = idx >> 5, d = idx & 31;
        kreg[i] = Qps[((size_t)key * BSZ + b) * DQK + h*DATT + d];
    }
    __syncthreads();

    // ---- Q fragments: [mt][ks][4] hi/lo ----
    uint32_t qa_hi[2][2][4], qa_lo[2][2][4];
    #pragma unroll
    for (int mt = 0; mt < 2; mt++) {
        int r = mt*16 + g;
        #pragma unroll
        for (int ks = 0; ks < 2; ks++) {
            int d = ks*16 + 2*t;
            uint2 p0 = *(const uint2*)&Qb[r*QPITCH + d];
            uint2 p1 = *(const uint2*)&Qb[(r+8)*QPITCH + d];
            uint2 p2 = *(const uint2*)&Qb[r*QPITCH + d + 8];
            uint2 p3 = *(const uint2*)&Qb[(r+8)*QPITCH + d + 8];
            qa_hi[mt][ks][0] = PERM_HI(p0.x, p0.y); qa_lo[mt][ks][0] = PERM_LO(p0.x, p0.y);
            qa_hi[mt][ks][1] = PERM_HI(p1.x, p1.y); qa_lo[mt][ks][1] = PERM_LO(p1.x, p1.y);
            qa_hi[mt][ks][2] = PERM_HI(p2.x, p2.y); qa_lo[mt][ks][2] = PERM_LO(p2.x, p2.y);
            qa_hi[mt][ks][3] = PERM_HI(p3.x, p3.y); qa_lo[mt][ks][3] = PERM_LO(p3.x, p3.y);
        }
    }

    // ---- phase 1: scores (scaled at store) ----
    for (int kt = 0; kt < 16; kt++) {
        #pragma unroll
        for (int i = 0; i < 8; i++) {
            int idx = 256*i + tid;
            buf[(idx >> 5)*KPITCH + (idx & 31)] = kreg[i];
        }
        __syncthreads();
        if (kt < 15) {
            int base = (kt + 1) * 64;
            #pragma unroll
            for (int i = 0; i < 8; i++) {
                int idx = 256*i + tid;
                int key = base + (idx >> 5), d = idx & 31;
                kreg[i] = Qps[((size_t)key * BSZ + b) * DQK + h*DATT + d];
            }
        }
        // B fragments: keys n = w*8 + g
        uint32_t bh[2][2], bl[2][2];
        {
            int key = w*8 + g;
            #pragma unroll
            for (int ks = 0; ks < 2; ks++) {
                int d = ks*16 + 2*t;
                uint2 p0 = *(const uint2*)&buf[key*KPITCH + d];
                uint2 p1 = *(const uint2*)&buf[key*KPITCH + d + 8];
                bh[ks][0] = PERM_HI(p0.x, p0.y); bl[ks][0] = PERM_LO(p0.x, p0.y);
                bh[ks][1] = PERM_HI(p1.x, p1.y); bl[ks][1] = PERM_LO(p1.x, p1.y);
            }
        }
        __syncthreads();
        #pragma unroll
        for (int mt = 0; mt < 2; mt++) {
            float c[4] = {0.f, 0.f, 0.f, 0.f};
            #pragma unroll
            for (int ks = 0; ks < 2; ks++) {
                mma_bf16(c, qa_hi[mt][ks], bh[ks]);
                mma_bf16(c, qa_hi[mt][ks], bl[ks]);
                mma_bf16(c, qa_lo[mt][ks], bh[ks]);
            }
            int row = mt*16 + g;
            int col = kt*64 + w*8 + 2*t;
            *(float2*)&Sf[row*SPITCH + col]     = make_float2(c[0]*scale, c[1]*scale);
            *(float2*)&Sf[(row+8)*SPITCH + col] = make_float2(c[2]*scale, c[3]*scale);
        }
    }
    __syncthreads();

    // ---- prefetch V stage 0 (packed u32) ----
    uint4 vreg[4];
    #pragma unroll
    for (int i = 0; i < 4; i++) {
        int f = 256*i + tid;
        int key = f >> 4, c4 = f & 15;
        vreg[i] = *(const uint4*)&Vps[((size_t)key * BSZ + b) * DEXP + h*HDIM + c4*4];
    }

    // ---- phase 2: softmax; write attn (float2) + packed P in place ----
    {
        for (int rr = 0; rr < 4; rr++) {
            int r = w + 8*rr;
            float* row = Sf + r*SPITCH;
            uint32_t* urow = Su + r*SPITCH;
            float m = -1e30f;
            for (int k = lane; k < 1024; k += 32) m = fmaxf(m, row[k]);
            #pragma unroll
            for (int o = 16; o; o >>= 1) m = fmaxf(m, __shfl_xor_sync(0xffffffffu, m, o));
            float s = 0.f;
            for (int k = lane; k < 1024; k += 32) {
                float e = __expf(row[k] - m);
                row[k] = e; s += e;
            }
            #pragma unroll
            for (int o = 16; o; o >>= 1) s += __shfl_xor_sync(0xffffffffu, s, o);
            float inv = 1.0f / s;
            __syncwarp();
            float* gp = attn_out ? attn_out + (((size_t)(b*NHEAD + h) * LL + (r0 + r)) * LL) : nullptr;
            #pragma unroll 4
            for (int i = 0; i < 16; i++) {
                int k = 2*lane + 64*i;
                float p0 = row[k] * inv, p1 = row[k+1] * inv;
                if (gp) *(float2*)&gp[k] = make_float2(p0, p1);
                urow[k]   = bf16_split_elem(p0);
                urow[k+1] = bf16_split_elem(p1);
            }
        }
    }

    // ---- phase 3: AV, ks-split: warp w -> ks = w>>1, nh = w&1 ----
    const int ks = w >> 1;
    const int nh = w & 1;
    float cav[2][4][4] = {};   // [mt][nt][4]
    for (int vt = 0; vt < 16; vt++) {
        #pragma unroll
        for (int i = 0; i < 4; i++) {
            int f = 256*i + tid;
            int key = f >> 4, c4 = f & 15;
            *(uint4*)&buf[key*VPITCH + c4*4] = vreg[i];
        }
        __syncthreads();
        if (vt < 15) {
            int base = (vt + 1) * 64;
            #pragma unroll
            for (int i = 0; i < 4; i++) {
                int f = 256*i + tid;
                int key = base + (f >> 4), c4 = f & 15;
                vreg[i] = *(const uint4*)&Vps[((size_t)key * BSZ + b) * DEXP + h*HDIM + c4*4];
            }
        }
        // a-frags for this warp's ks only
        uint32_t ah[2][4], al[2][4];
        #pragma unroll
        for (int mt = 0; mt < 2; mt++) {
            int r = mt*16 + g;
            int d = vt*64 + ks*16 + 2*t;
            uint2 p0 = *(const uint2*)&Su[r*SPITCH + d];
            uint2 p1 = *(const uint2*)&Su[(r+8)*SPITCH + d];
            uint2 p2 = *(const uint2*)&Su[r*SPITCH + d + 8];
            uint2 p3 = *(const uint2*)&Su[(r+8)*SPITCH + d + 8];
            ah[mt][0] = PERM_HI(p0.x, p0.y); al[mt][0] = PERM_LO(p0.x, p0.y);
            ah[mt][1] = PERM_HI(p1.x, p1.y); al[mt][1] = PERM_LO(p1.x, p1.y);
            ah[mt][2] = PERM_HI(p2.x, p2.y); al[mt][2] = PERM_LO(p2.x, p2.y);
            ah[mt][3] = PERM_HI(p3.x, p3.y); al[mt][3] = PERM_LO(p3.x, p3.y);
        }
        // b-frags + mma over 4 n-tiles in this warp's n-half
        #pragma unroll
        for (int nt = 0; nt < 4; nt++) {
            int nn = nh*32 + nt*8 + g;
            int kk = ks*16 + 2*t;
            uint32_t q0 = buf[kk*VPITCH + nn];
            uint32_t q1 = buf[(kk+1)*VPITCH + nn];
            uint32_t q2 = buf[(kk+8)*VPITCH + nn];
            uint32_t q3 = buf[(kk+9)*VPITCH + nn];
            uint32_t bfh[2], bfl[2];
            bfh[0] = PERM_HI(q0, q1); bfl[0] = PERM_LO(q0, q1);
            bfh[1] = PERM_HI(q2, q3); bfl[1] = PERM_LO(q2, q3);
            #pragma unroll
            for (int mt = 0; mt < 2; mt++) {
                mma_bf16(cav[mt][nt], ah[mt], bfh);
                mma_bf16(cav[mt][nt], ah[mt], bfl);
                mma_bf16(cav[mt][nt], al[mt], bfh);
            }
        }
        __syncthreads();
    }

    // ---- reduction across ks groups (overlay R on S region) ----
    #pragma unroll
    for (int mt = 0; mt < 2; mt++) {
        int row = mt*16 + g;
        #pragma unroll
        for (int nt = 0; nt < 4; nt++) {
            int col = nh*32 + nt*8 + 2*t;
            *(float2*)&R[((ks*32 + row)*64) + col]     = make_float2(cav[mt][nt][0], cav[mt][nt][1]);
            *(float2*)&R[((ks*32 + row + 8)*64) + col] = make_float2(cav[mt][nt][2], cav[mt][nt][3]);
        }
    }
    __syncthreads();

    // ---- final: sum 4 partials, U-gate, write ----
    {
        int sub = lane >> 4;           // 0/1
        int c   = 2*(lane & 15);       // 0..30 step 2
        #pragma unroll
        for (int it = 0; it < 2; it++) {
            int rr = w*4 + 2*it + sub;
            float2 s = make_float2(0.f, 0.f);
            #pragma unroll
            for (int kq = 0; kq < 4; kq++) {
                float2 p = *(const float2*)&R[((kq*32 + rr)*64) + c];
                s.x += p.x; s.y += p.y;
                float2 p2 = *(const float2*)&R[((kq*32 + rr)*64) + c + 32];
                // accumulate second half below
                if (kq == 0) { /* placeholder */ }
                (void)p2;
            }
            // handle both 32-col halves explicitly
            float2 s2 = make_float2(0.f, 0.f);
            #pragma unroll
            for (int kq = 0; kq < 4; kq++) {
                float2 p2 = *(const float2*)&R[((kq*32 + rr)*64) + c + 32];
                s2.x += p2.x; s2.y += p2.y;
            }
            size_t gb = ((size_t)(r0 + rr) * BSZ + b) * DEXP + h*HDIM;
            float2 u  = *(const float2*)&Uc[gb + c];
            *(float2*)&Gout[gb + c] = make_float2(s.x*u.x, s.y*u.y);
            float2 u2 = *(const float2*)&Uc[gb + c + 32];
            *(float2*)&Gout[gb + c + 32] = make_float2(s2.x*u2.x, s2.y*u2.y);
        }
    }
}

// ---------------- depthwise 5x5 conv ----------------
__global__ __launch_bounds__(256) void dwconv_kernel(
    const float* __restrict__ X, const float* __restrict__ Wc, float* __restrict__ Y)
{
    extern __shared__ float sm[];
    float* xs = sm;             // [1024][33]
    float* ws = sm + 1024*33;   // [32][25]
    const int c0 = blockIdx.x * 32, b = blockIdx.y;
    const int tid = threadIdx.x;

    for (int idx = tid; idx < 1024*32; idx += 256) {
        int t = idx >> 5, c = idx & 31;
        xs[t*33 + c] = X[((size_t)t * BSZ + b) * DEXP + c0 + c];
    }
    for (int idx = tid; idx < 32*25; idx += 256) {
        int c = idx / 25, t = idx % 25;
        ws[c*25 + t] = Wc[(size_t)(c0 + c) * 25 + t];
    }
    __syncthreads();

    const int c = tid & 31, pr = tid >> 5;
    for (int s = 0; s < 128; s++) {
        int pos = pr + 8*s;
        int i = pos >> 5, j = pos & 31;
        float acc = 0.f;
        #pragma unroll
        for (int di = 0; di < 5; di++) {
            int ii = i + di - 2;
            if (ii < 0 || ii >= 32) continue;
            #pragma unroll
            for (int dj = 0; dj < 5; dj++) {
                int jj = j + dj - 2;
                if (jj < 0 || jj >= 32) continue;
                acc += xs[(ii*32 + jj)*33 + c] * ws[c*25 + di*5 + dj];
            }
        }
        Y[((size_t)pos * BSZ + b) * DEXP + c0 + c] = acc;
    }
}

// ---------------- launch ----------------
extern "C" void kernel_launch(void* const* d_in, const int* in_sizes, int n_in,
                              void* d_out, int out_size)
{
    const float* Q   = (const float*)d_in[0];
    const float* V   = (const float*)d_in[2];
    const float* U   = (const float*)d_in[3];
    const float* Wqk = (const float*)d_in[4];
    const float* bqk = (const float*)d_in[5];
    const float* Wv1 = (const float*)d_in[6];
    const float* bv1 = (const float*)d_in[7];
    const float* Wv2 = (const float*)d_in[8];
    const float* bv2 = (const float*)d_in[9];
    const float* Wu1 = (const float*)d_in[10];
    const float* bu1 = (const float*)d_in[11];
    const float* Wu2 = (const float*)d_in[12];
    const float* bu2 = (const float*)d_in[13];
    const float* Wcv = (const float*)d_in[14];
    const float* Wp  = (const float*)d_in[15];
    const float* bp  = (const float*)d_in[16];

    float* out  = (float*)d_out;
    float* attn = (out_size > MROWS*DQK) ? out + (size_t)MROWS*DQK : nullptr;

    uint32_t *Qps, *Vps;
    float *Uc, *G, *Y;
    cudaGetSymbolAddress((void**)&Qps, g_Qps);
    cudaGetSymbolAddress((void**)&Vps, g_Vps);
    cudaGetSymbolAddress((void**)&Uc,  g_Uc);
    cudaGetSymbolAddress((void**)&G,   g_G);
    cudaGetSymbolAddress((void**)&Y,   g_Y);

    const size_t ATTN_SMEM = (size_t)(32*SPITCH + 64*VPITCH + 32*QPITCH) * 4; // ~155 KB
    const size_t CONV_SMEM = (size_t)(1024*33 + 32*25) * sizeof(float);
    cudaFuncSetAttribute(attn_kernel,   cudaFuncAttributeMaxDynamicSharedMemorySize, (int)ATTN_SMEM);
    cudaFuncSetAttribute(dwconv_kernel, cudaFuncAttributeMaxDynamicSharedMemorySize, (int)CONV_SMEM);

    // 1) Qp = Q @ Wqk + bqk  -> packed u32
    {
        dim3 grid(DQK/64, MROWS/64);
        gemm_bias_kernel<<<grid, 256>>>(Q, Wqk, bqk, Qps, MROWS, DQK, DQK, 1);
    }
    // 2) Vc packed, Uc fp32
    {
        dim3 grid(16, MROWS/64);
        gated_proj_kernel<<<grid, 256>>>(V, Wv1, bv1, Wv2, bv2, Vps, 1);
        gated_proj_kernel<<<grid, 256>>>(U, Wu1, bu1, Wu2, bu2, Uc, 0);
    }
    // 3) attention
    {
        dim3 grid(LL/32, NHEAD, BSZ);
        attn_kernel<<<grid, 256, ATTN_SMEM>>>(Qps, Vps, Uc, attn, G);
    }
    // 4) depthwise conv
    {
        dim3 grid(16, BSZ);
        dwconv_kernel<<<grid, 256, CONV_SMEM>>>(G, Wcv, Y);
    }
    // 5) outputs = Y @ Wp + bp
    {
        dim3 grid(DQK/64, MROWS/64);
        gemm_bias_kernel<<<grid, 256>>>(Y, Wp, bp, out, MROWS, DQK, DEXP, 0);
    }
}

// round 7
// speedup vs baseline: 2.1579x; 1.1404x over previous
#include <cuda_runtime.h>
#include <cuda_bf16.h>
#include <math.h>
#include <stdint.h>

#define LL    1024
#define BSZ   8
#define DQK   256
#define DEXP  512
#define NHEAD 8
#define HDIM  64
#define DATT  32
#define MROWS (LL*BSZ)   // 8192
#define HALF_OUT 256
#define SPITCH 1032      // S pitch (u32/f32)
#define KPITCH 40        // K-tile pitch (u32)
#define QPITCH 40        // Q-tile pitch (u32)
#define VPITCH 68        // V-tile pitch (u32)

// ---------------- scratch ----------------
__device__ __align__(256) uint32_t g_Qps[MROWS*DQK];   // packed bf16(hi,lo) Qp
__device__ __align__(256) uint32_t g_Vps[MROWS*DEXP];  // packed bf16(hi,lo) Vc
__device__ __align__(256) float    g_Uc [MROWS*DEXP];
__device__ __align__(256) float    g_G  [MROWS*DEXP];
__device__ __align__(256) float    g_Y  [MROWS*DEXP];

// ---------------- helpers ----------------
__device__ __forceinline__ uint32_t bf16_split_elem(float x) {
    __nv_bfloat16 hb = __float2bfloat16_rn(x);
    float hf = __bfloat162float(hb);
    __nv_bfloat16 lb = __float2bfloat16_rn(x - hf);
    return ((uint32_t)__bfloat16_as_ushort(lb) << 16) | (uint32_t)__bfloat16_as_ushort(hb);
}

__device__ __forceinline__ void mma_bf16(float* c, const uint32_t* a, const uint32_t* b) {
    asm volatile(
        "mma.sync.aligned.m16n8k16.row.col.f32.bf16.bf16.f32 "
        "{%0,%1,%2,%3},{%4,%5,%6,%7},{%8,%9},{%0,%1,%2,%3};"
        : "+f"(c[0]), "+f"(c[1]), "+f"(c[2]), "+f"(c[3])
        : "r"(a[0]), "r"(a[1]), "r"(a[2]), "r"(a[3]), "r"(b[0]), "r"(b[1]));
}

#define PERM_HI(p0, p1) __byte_perm((p0), (p1), 0x5410)
#define PERM_LO(p0, p1) __byte_perm((p0), (p1), 0x7632)

// ---------------- generic tiled GEMM + bias ----------------
__global__ __launch_bounds__(256) void gemm_bias_kernel(
    const float* __restrict__ A, const float* __restrict__ B,
    const float* __restrict__ bias, void* __restrict__ Cv,
    int M, int N, int K, int mode)
{
    __shared__ float As[16][65];
    __shared__ float Bs[16][64];
    const int m0 = blockIdx.y * 64, n0 = blockIdx.x * 64;
    const int tid = threadIdx.x;
    const int tx = tid & 15, ty = tid >> 4;
    float acc[4][4] = {};

    for (int k0 = 0; k0 < K; k0 += 16) {
        #pragma unroll
        for (int idx = tid; idx < 64*16; idx += 256) {
            int r = idx >> 4, kk = idx & 15;
            As[kk][r] = A[(size_t)(m0 + r) * K + k0 + kk];
        }
        #pragma unroll
        for (int idx = tid; idx < 16*64; idx += 256) {
            int kk = idx >> 6, c = idx & 63;
            Bs[kk][c] = B[(size_t)(k0 + kk) * N + n0 + c];
        }
        __syncthreads();
        #pragma unroll
        for (int kk = 0; kk < 16; kk++) {
            float a[4], b[4];
            #pragma unroll
            for (int i = 0; i < 4; i++) a[i] = As[kk][ty + 16*i];
            #pragma unroll
            for (int j = 0; j < 4; j++) b[j] = Bs[kk][tx + 16*j];
            #pragma unroll
            for (int i = 0; i < 4; i++)
                #pragma unroll
                for (int j = 0; j < 4; j++)
                    acc[i][j] += a[i] * b[j];
        }
        __syncthreads();
    }
    #pragma unroll
    for (int i = 0; i < 4; i++) {
        int r = m0 + ty + 16*i;
        #pragma unroll
        for (int j = 0; j < 4; j++) {
            int c = n0 + tx + 16*j;
            float v = acc[i][j] + bias[c];
            if (mode == 0) ((float*)Cv)[(size_t)r * N + c] = v;
            else           ((uint32_t*)Cv)[(size_t)r * N + c] = bf16_split_elem(v);
        }
    }
}

// ---------------- gated half-projection + SiLU ----------------
__global__ __launch_bounds__(256) void gated_proj_kernel(
    const float* __restrict__ X,
    const float* __restrict__ W1, const float* __restrict__ b1,
    const float* __restrict__ W2, const float* __restrict__ b2,
    void* __restrict__ Yv, int packed)
{
    __shared__ float As[16][65];
    __shared__ float Bs[16][32];
    const int c0   = blockIdx.x * 32;
    const int head = c0 >> 6;
    const int is2  = (c0 >> 5) & 1;
    const float* W  = is2 ? W2 : W1;
    const float* bb = is2 ? b2 : b1;
    const int wc0 = head * 32;
    const float* Ain = X + (is2 ? 128 : 0);
    const int m0 = blockIdx.y * 64;
    const int tid = threadIdx.x;
    const int tx = tid & 31, ty = tid >> 5;
    float acc[8] = {};

    for (int k0 = 0; k0 < 128; k0 += 16) {
        #pragma unroll
        for (int idx = tid; idx < 64*16; idx += 256) {
            int r = idx >> 4, kk = idx & 15;
            As[kk][r] = Ain[(size_t)(m0 + r) * 256 + k0 + kk];
        }
        #pragma unroll
        for (int idx = tid; idx < 16*32; idx += 256) {
            int kk = idx >> 5, c = idx & 31;
            Bs[kk][c] = W[(size_t)(k0 + kk) * HALF_OUT + wc0 + c];
        }
        __syncthreads();
        #pragma unroll
        for (int kk = 0; kk < 16; kk++) {
            float bv = Bs[kk][tx];
            #pragma unroll
            for (int i = 0; i < 8; i++)
                acc[i] += As[kk][ty + 8*i] * bv;
        }
        __syncthreads();
    }
    float bias = bb[wc0 + tx];
    #pragma unroll
    for (int i = 0; i < 8; i++) {
        int r = m0 + ty + 8*i;
        float v = acc[i] + bias;
        float y = v / (1.0f + __expf(-v));
        if (packed) ((uint32_t*)Yv)[(size_t)r * DEXP + c0 + tx] = bf16_split_elem(y);
        else        ((float*)Yv)[(size_t)r * DEXP + c0 + tx] = y;
    }
}

// ---------------- fused attention (bf16x3, 512 threads = 16 warps) ----------------
// grid: (32 row-tiles, NHEAD, BSZ)
__global__ __launch_bounds__(512) void attn_kernel(
    const uint32_t* __restrict__ Qps, const uint32_t* __restrict__ Vps,
    const float* __restrict__ Uc, float* __restrict__ attn_out,
    float* __restrict__ Gout)
{
    extern __shared__ float sm[];
    float*    Sf  = sm;                            // 32 * SPITCH
    uint32_t* Su  = (uint32_t*)sm;
    uint32_t* buf = (uint32_t*)(sm + 32*SPITCH);   // K: 128*KPITCH / V: 64*VPITCH
    uint32_t* Qb  = buf + 128*KPITCH;              // 32*QPITCH
    float*    R   = sm;                            // reduction overlay [4][32][64]

    const int r0 = blockIdx.x * 32;
    const int h  = blockIdx.y, b = blockIdx.z;
    const int tid  = threadIdx.x;
    const int lane = tid & 31;
    const int w    = tid >> 5;          // 0..15
    const int g    = lane >> 2;
    const int t    = lane & 3;
    const float scale = 0.17677669529663687f;   // 1/sqrt(32)

    // ---- load Q tile; prefetch K stage 0 (128 keys) ----
    #pragma unroll
    for (int i = 0; i < 2; i++) {
        int idx = 512*i + tid;
        int r = idx >> 5, d = idx & 31;
        Qb[r*QPITCH + d] = Qps[((size_t)(r0 + r) * BSZ + b) * DQK + h*DATT + d];
    }
    uint32_t kreg[8];
    #pragma unroll
    for (int i = 0; i < 8; i++) {
        int idx = 512*i + tid;
        int key = idx >> 5, d = idx & 31;
        kreg[i] = Qps[((size_t)key * BSZ + b) * DQK + h*DATT + d];
    }
    __syncthreads();

    // ---- Q fragments ----
    uint32_t qa_hi[2][2][4], qa_lo[2][2][4];
    #pragma unroll
    for (int mt = 0; mt < 2; mt++) {
        int r = mt*16 + g;
        #pragma unroll
        for (int ks = 0; ks < 2; ks++) {
            int d = ks*16 + 2*t;
            uint2 p0 = *(const uint2*)&Qb[r*QPITCH + d];
            uint2 p1 = *(const uint2*)&Qb[(r+8)*QPITCH + d];
            uint2 p2 = *(const uint2*)&Qb[r*QPITCH + d + 8];
            uint2 p3 = *(const uint2*)&Qb[(r+8)*QPITCH + d + 8];
            qa_hi[mt][ks][0] = PERM_HI(p0.x, p0.y); qa_lo[mt][ks][0] = PERM_LO(p0.x, p0.y);
            qa_hi[mt][ks][1] = PERM_HI(p1.x, p1.y); qa_lo[mt][ks][1] = PERM_LO(p1.x, p1.y);
            qa_hi[mt][ks][2] = PERM_HI(p2.x, p2.y); qa_lo[mt][ks][2] = PERM_LO(p2.x, p2.y);
            qa_hi[mt][ks][3] = PERM_HI(p3.x, p3.y); qa_lo[mt][ks][3] = PERM_LO(p3.x, p3.y);
        }
    }

    // ---- phase 1: scores; 8 stages of 128 keys; warp w owns n8 slice ----
    for (int kt = 0; kt < 8; kt++) {
        #pragma unroll
        for (int i = 0; i < 8; i++) {
            int idx = 512*i + tid;
            buf[(idx >> 5)*KPITCH + (idx & 31)] = kreg[i];
        }
        __syncthreads();
        if (kt < 7) {
            int base = (kt + 1) * 128;
            #pragma unroll
            for (int i = 0; i < 8; i++) {
                int idx = 512*i + tid;
                int key = base + (idx >> 5), d = idx & 31;
                kreg[i] = Qps[((size_t)key * BSZ + b) * DQK + h*DATT + d];
            }
        }
        uint32_t bh[2][2], bl[2][2];
        {
            int key = w*8 + g;
            #pragma unroll
            for (int ks = 0; ks < 2; ks++) {
                int d = ks*16 + 2*t;
                uint2 p0 = *(const uint2*)&buf[key*KPITCH + d];
                uint2 p1 = *(const uint2*)&buf[key*KPITCH + d + 8];
                bh[ks][0] = PERM_HI(p0.x, p0.y); bl[ks][0] = PERM_LO(p0.x, p0.y);
                bh[ks][1] = PERM_HI(p1.x, p1.y); bl[ks][1] = PERM_LO(p1.x, p1.y);
            }
        }
        __syncthreads();
        #pragma unroll
        for (int mt = 0; mt < 2; mt++) {
            float c[4] = {0.f, 0.f, 0.f, 0.f};
            #pragma unroll
            for (int ks = 0; ks < 2; ks++) {
                mma_bf16(c, qa_hi[mt][ks], bh[ks]);
                mma_bf16(c, qa_hi[mt][ks], bl[ks]);
                mma_bf16(c, qa_lo[mt][ks], bh[ks]);
            }
            int row = mt*16 + g;
            int col = kt*128 + w*8 + 2*t;
            *(float2*)&Sf[row*SPITCH + col]     = make_float2(c[0]*scale, c[1]*scale);
            *(float2*)&Sf[(row+8)*SPITCH + col] = make_float2(c[2]*scale, c[3]*scale);
        }
    }
    __syncthreads();

    // ---- prefetch V stage 0 (64 keys x 64 cols) ----
    uint4 vreg[2];
    #pragma unroll
    for (int i = 0; i < 2; i++) {
        int f = 512*i + tid;
        int key = f >> 4, c4 = f & 15;
        vreg[i] = *(const uint4*)&Vps[((size_t)key * BSZ + b) * DEXP + h*HDIM + c4*4];
    }

    // ---- phase 2: softmax (2 rows per warp); write attn + packed P ----
    {
        for (int rr = 0; rr < 2; rr++) {
            int r = 2*w + rr;
            float* row = Sf + r*SPITCH;
            uint32_t* urow = Su + r*SPITCH;
            float m = -1e30f;
            for (int k = lane; k < 1024; k += 32) m = fmaxf(m, row[k]);
            #pragma unroll
            for (int o = 16; o; o >>= 1) m = fmaxf(m, __shfl_xor_sync(0xffffffffu, m, o));
            float s = 0.f;
            for (int k = lane; k < 1024; k += 32) {
                float e = __expf(row[k] - m);
                row[k] = e; s += e;
            }
            #pragma unroll
            for (int o = 16; o; o >>= 1) s += __shfl_xor_sync(0xffffffffu, s, o);
            float inv = 1.0f / s;
            __syncwarp();
            float* gp = attn_out ? attn_out + (((size_t)(b*NHEAD + h) * LL + (r0 + r)) * LL) : nullptr;
            #pragma unroll 4
            for (int i = 0; i < 16; i++) {
                int k = 2*lane + 64*i;
                float p0 = row[k] * inv, p1 = row[k+1] * inv;
                if (gp) *(float2*)&gp[k] = make_float2(p0, p1);
                urow[k]   = bf16_split_elem(p0);
                urow[k+1] = bf16_split_elem(p1);
            }
        }
    }

    // ---- phase 3: AV; warp = (ks = w>>2, nq = w&3); 16 stages of 64 keys ----
    const int ks = w >> 2;     // 0..3 -> k16 block within 64-key stage
    const int nq = w & 3;      // 0..3 -> 16-col quarter
    float cav[2][2][4] = {};   // [mt][nt][4]
    for (int vt = 0; vt < 16; vt++) {
        #pragma unroll
        for (int i = 0; i < 2; i++) {
            int f = 512*i + tid;
            int key = f >> 4, c4 = f & 15;
            *(uint4*)&buf[key*VPITCH + c4*4] = vreg[i];
        }
        __syncthreads();
        if (vt < 15) {
            int base = (vt + 1) * 64;
            #pragma unroll
            for (int i = 0; i < 2; i++) {
                int f = 512*i + tid;
                int key = base + (f >> 4), c4 = f & 15;
                vreg[i] = *(const uint4*)&Vps[((size_t)key * BSZ + b) * DEXP + h*HDIM + c4*4];
            }
        }
        // a-frags for this warp's k16 block
        uint32_t ah[2][4], al[2][4];
        #pragma unroll
        for (int mt = 0; mt < 2; mt++) {
            int r = mt*16 + g;
            int d = vt*64 + ks*16 + 2*t;
            uint2 p0 = *(const uint2*)&Su[r*SPITCH + d];
            uint2 p1 = *(const uint2*)&Su[(r+8)*SPITCH + d];
            uint2 p2 = *(const uint2*)&Su[r*SPITCH + d + 8];
            uint2 p3 = *(const uint2*)&Su[(r+8)*SPITCH + d + 8];
            ah[mt][0] = PERM_HI(p0.x, p0.y); al[mt][0] = PERM_LO(p0.x, p0.y);
            ah[mt][1] = PERM_HI(p1.x, p1.y); al[mt][1] = PERM_LO(p1.x, p1.y);
            ah[mt][2] = PERM_HI(p2.x, p2.y); al[mt][2] = PERM_LO(p2.x, p2.y);
            ah[mt][3] = PERM_HI(p3.x, p3.y); al[mt][3] = PERM_LO(p3.x, p3.y);
        }
        #pragma unroll
        for (int nt = 0; nt < 2; nt++) {
            int nn = nq*16 + nt*8 + g;
            int kk = ks*16 + 2*t;
            uint32_t q0 = buf[kk*VPITCH + nn];
            uint32_t q1 = buf[(kk+1)*VPITCH + nn];
            uint32_t q2 = buf[(kk+8)*VPITCH + nn];
            uint32_t q3 = buf[(kk+9)*VPITCH + nn];
            uint32_t bfh[2], bfl[2];
            bfh[0] = PERM_HI(q0, q1); bfl[0] = PERM_LO(q0, q1);
            bfh[1] = PERM_HI(q2, q3); bfl[1] = PERM_LO(q2, q3);
            #pragma unroll
            for (int mt = 0; mt < 2; mt++) {
                mma_bf16(cav[mt][nt], ah[mt], bfh);
                mma_bf16(cav[mt][nt], ah[mt], bfl);
                mma_bf16(cav[mt][nt], al[mt], bfh);
            }
        }
        __syncthreads();
    }

    // ---- reduction across ks groups (overlay R) ----
    #pragma unroll
    for (int mt = 0; mt < 2; mt++) {
        int row = mt*16 + g;
        #pragma unroll
        for (int nt = 0; nt < 2; nt++) {
            int col = nq*16 + nt*8 + 2*t;
            *(float2*)&R[((ks*32 + row)*64) + col]     = make_float2(cav[mt][nt][0], cav[mt][nt][1]);
            *(float2*)&R[((ks*32 + row + 8)*64) + col] = make_float2(cav[mt][nt][2], cav[mt][nt][3]);
        }
    }
    __syncthreads();

    // ---- final: sum 4 partials, U-gate, write ----
    {
        int rr = tid >> 4;          // 0..31
        int c  = 2*(tid & 15);      // 0..30
        float2 s  = make_float2(0.f, 0.f);
        float2 s2 = make_float2(0.f, 0.f);
        #pragma unroll
        for (int kq = 0; kq < 4; kq++) {
            float2 p  = *(const float2*)&R[((kq*32 + rr)*64) + c];
            float2 p2 = *(const float2*)&R[((kq*32 + rr)*64) + c + 32];
            s.x += p.x;  s.y += p.y;
            s2.x += p2.x; s2.y += p2.y;
        }
        size_t gb = ((size_t)(r0 + rr) * BSZ + b) * DEXP + h*HDIM;
        float2 u  = *(const float2*)&Uc[gb + c];
        *(float2*)&Gout[gb + c] = make_float2(s.x*u.x, s.y*u.y);
        float2 u2 = *(const float2*)&Uc[gb + c + 32];
        *(float2*)&Gout[gb + c + 32] = make_float2(s2.x*u2.x, s2.y*u2.y);
    }
}

// ---------------- depthwise 5x5 conv ----------------
__global__ __launch_bounds__(256) void dwconv_kernel(
    const float* __restrict__ X, const float* __restrict__ Wc, float* __restrict__ Y)
{
    extern __shared__ float sm[];
    float* xs = sm;             // [1024][33]
    float* ws = sm + 1024*33;   // [32][25]
    const int c0 = blockIdx.x * 32, b = blockIdx.y;
    const int tid = threadIdx.x;

    for (int idx = tid; idx < 1024*32; idx += 256) {
        int t = idx >> 5, c = idx & 31;
        xs[t*33 + c] = X[((size_t)t * BSZ + b) * DEXP + c0 + c];
    }
    for (int idx = tid; idx < 32*25; idx += 256) {
        int c = idx / 25, t = idx % 25;
        ws[c*25 + t] = Wc[(size_t)(c0 + c) * 25 + t];
    }
    __syncthreads();

    const int c = tid & 31, pr = tid >> 5;
    for (int s = 0; s < 128; s++) {
        int pos = pr + 8*s;
        int i = pos >> 5, j = pos & 31;
        float acc = 0.f;
        #pragma unroll
        for (int di = 0; di < 5; di++) {
            int ii = i + di - 2;
            if (ii < 0 || ii >= 32) continue;
            #pragma unroll
            for (int dj = 0; dj < 5; dj++) {
                int jj = j + dj - 2;
                if (jj < 0 || jj >= 32) continue;
                acc += xs[(ii*32 + jj)*33 + c] * ws[c*25 + di*5 + dj];
            }
        }
        Y[((size_t)pos * BSZ + b) * DEXP + c0 + c] = acc;
    }
}

// ---------------- launch ----------------
extern "C" void kernel_launch(void* const* d_in, const int* in_sizes, int n_in,
                              void* d_out, int out_size)
{
    const float* Q   = (const float*)d_in[0];
    const float* V   = (const float*)d_in[2];
    const float* U   = (const float*)d_in[3];
    const float* Wqk = (const float*)d_in[4];
    const float* bqk = (const float*)d_in[5];
    const float* Wv1 = (const float*)d_in[6];
    const float* bv1 = (const float*)d_in[7];
    const float* Wv2 = (const float*)d_in[8];
    const float* bv2 = (const float*)d_in[9];
    const float* Wu1 = (const float*)d_in[10];
    const float* bu1 = (const float*)d_in[11];
    const float* Wu2 = (const float*)d_in[12];
    const float* bu2 = (const float*)d_in[13];
    const float* Wcv = (const float*)d_in[14];
    const float* Wp  = (const float*)d_in[15];
    const float* bp  = (const float*)d_in[16];

    float* out  = (float*)d_out;
    float* attn = (out_size > MROWS*DQK) ? out + (size_t)MROWS*DQK : nullptr;

    uint32_t *Qps, *Vps;
    float *Uc, *G, *Y;
    cudaGetSymbolAddress((void**)&Qps, g_Qps);
    cudaGetSymbolAddress((void**)&Vps, g_Vps);
    cudaGetSymbolAddress((void**)&Uc,  g_Uc);
    cudaGetSymbolAddress((void**)&G,   g_G);
    cudaGetSymbolAddress((void**)&Y,   g_Y);

    const size_t ATTN_SMEM = (size_t)(32*SPITCH + 128*KPITCH + 32*QPITCH) * 4; // ~158 KB
    const size_t CONV_SMEM = (size_t)(1024*33 + 32*25) * sizeof(float);
    cudaFuncSetAttribute(attn_kernel,   cudaFuncAttributeMaxDynamicSharedMemorySize, (int)ATTN_SMEM);
    cudaFuncSetAttribute(dwconv_kernel, cudaFuncAttributeMaxDynamicSharedMemorySize, (int)CONV_SMEM);

    // 1) Qp = Q @ Wqk + bqk -> packed u32
    {
        dim3 grid(DQK/64, MROWS/64);
        gemm_bias_kernel<<<grid, 256>>>(Q, Wqk, bqk, Qps, MROWS, DQK, DQK, 1);
    }
    // 2) Vc packed, Uc fp32
    {
        dim3 grid(16, MROWS/64);
        gated_proj_kernel<<<grid, 256>>>(V, Wv1, bv1, Wv2, bv2, Vps, 1);
        gated_proj_kernel<<<grid, 256>>>(U, Wu1, bu1, Wu2, bu2, Uc, 0);
    }
    // 3) attention
    {
        dim3 grid(LL/32, NHEAD, BSZ);
        attn_kernel<<<grid, 512, ATTN_SMEM>>>(Qps, Vps, Uc, attn, G);
    }
    // 4) depthwise conv
    {
        dim3 grid(16, BSZ);
        dwconv_kernel<<<grid, 256, CONV_SMEM>>>(G, Wcv, Y);
    }
    // 5) outputs = Y @ Wp + bp
    {
        dim3 grid(DQK/64, MROWS/64);
        gemm_bias_kernel<<<grid, 256>>>(Y, Wp, bp, out, MROWS, DQK, DEXP, 0);
    }
}

// round 9
// speedup vs baseline: 3.0797x; 1.4272x over previous
#include <cuda_runtime.h>
#include <cuda_bf16.h>
#include <math.h>
#include <stdint.h>

#define LL    1024
#define BSZ   8
#define DQK   256
#define DEXP  512
#define NHEAD 8
#define HDIM  64
#define DATT  32
#define MROWS (LL*BSZ)   // 8192
#define HALF_OUT 256
#define SPITCH 1032      // S pitch (u32/f32)
#define KPITCH 40        // K-tile pitch (u32)
#define QPITCH 40        // Q-tile pitch (u32)
#define VPITCH 68        // V-tile pitch (u32)

// ---------------- scratch ----------------
__device__ __align__(256) uint32_t g_Qps[MROWS*DQK];   // packed bf16(hi,lo) Qp
__device__ __align__(256) uint32_t g_Vps[MROWS*DEXP];  // packed bf16(hi,lo) Vc
__device__ __align__(256) float    g_Uc [MROWS*DEXP];
__device__ __align__(256) float    g_G  [MROWS*DEXP];
__device__ __align__(256) float    g_Y  [MROWS*DEXP];

// ---------------- helpers ----------------
__device__ __forceinline__ uint32_t bf16_split_elem(float x) {
    __nv_bfloat16 hb = __float2bfloat16_rn(x);
    float hf = __bfloat162float(hb);
    __nv_bfloat16 lb = __float2bfloat16_rn(x - hf);
    return ((uint32_t)__bfloat16_as_ushort(lb) << 16) | (uint32_t)__bfloat16_as_ushort(hb);
}

__device__ __forceinline__ void mma_bf16(float* c, const uint32_t* a, const uint32_t* b) {
    asm volatile(
        "mma.sync.aligned.m16n8k16.row.col.f32.bf16.bf16.f32 "
        "{%0,%1,%2,%3},{%4,%5,%6,%7},{%8,%9},{%0,%1,%2,%3};"
        : "+f"(c[0]), "+f"(c[1]), "+f"(c[2]), "+f"(c[3])
        : "r"(a[0]), "r"(a[1]), "r"(a[2]), "r"(a[3]), "r"(b[0]), "r"(b[1]));
}

#define PERM_HI(p0, p1) __byte_perm((p0), (p1), 0x5410)
#define PERM_LO(p0, p1) __byte_perm((p0), (p1), 0x7632)

// ---------------- tensor-core GEMM + bias: C[M,N] = A[M,K]@B[K,N] + bias ----------------
// CTA tile 64x64, 8 warps (2m x 4n quarters), K-stage 32, bf16x3.
// mode 0: fp32 out; mode 1: packed u32 out.
__global__ __launch_bounds__(256) void mma_gemm_kernel(
    const float* __restrict__ A, const float* __restrict__ B,
    const float* __restrict__ bias, void* __restrict__ Cv,
    int M, int N, int K, int mode)
{
    __shared__ uint32_t As[64*40];   // [m][k] packed
    __shared__ uint32_t Bs[32*68];   // [k][n] packed
    const int m0 = blockIdx.y * 64, n0 = blockIdx.x * 64;
    const int tid = threadIdx.x, lane = tid & 31, w = tid >> 5;
    const int g = lane >> 2, t = lane & 3;
    const int mw = w >> 2, nq = w & 3;

    float aReg[8], bReg[8];
    #pragma unroll
    for (int i = 0; i < 8; i++) {
        int idx = 256*i + tid;
        aReg[i] = A[(size_t)(m0 + (idx >> 5)) * K + (idx & 31)];
        bReg[i] = B[(size_t)(idx >> 6) * N + n0 + (idx & 63)];
    }
    float acc[2][2][4] = {};

    for (int k0 = 0; k0 < K; k0 += 32) {
        #pragma unroll
        for (int i = 0; i < 8; i++) {
            int idx = 256*i + tid;
            As[(idx >> 5)*40 + (idx & 31)] = bf16_split_elem(aReg[i]);
            Bs[(idx >> 6)*68 + (idx & 63)] = bf16_split_elem(bReg[i]);
        }
        __syncthreads();
        if (k0 + 32 < K) {
            #pragma unroll
            for (int i = 0; i < 8; i++) {
                int idx = 256*i + tid;
                aReg[i] = A[(size_t)(m0 + (idx >> 5)) * K + k0 + 32 + (idx & 31)];
                bReg[i] = B[(size_t)(k0 + 32 + (idx >> 6)) * N + n0 + (idx & 63)];
            }
        }
        #pragma unroll
        for (int ks = 0; ks < 2; ks++) {
            uint32_t ah[2][4], al[2][4];
            #pragma unroll
            for (int mt = 0; mt < 2; mt++) {
                int r = mw*32 + mt*16 + g;
                int d = ks*16 + 2*t;
                uint2 p0 = *(const uint2*)&As[r*40 + d];
                uint2 p1 = *(const uint2*)&As[(r+8)*40 + d];
                uint2 p2 = *(const uint2*)&As[r*40 + d + 8];
                uint2 p3 = *(const uint2*)&As[(r+8)*40 + d + 8];
                ah[mt][0] = PERM_HI(p0.x, p0.y); al[mt][0] = PERM_LO(p0.x, p0.y);
                ah[mt][1] = PERM_HI(p1.x, p1.y); al[mt][1] = PERM_LO(p1.x, p1.y);
                ah[mt][2] = PERM_HI(p2.x, p2.y); al[mt][2] = PERM_LO(p2.x, p2.y);
                ah[mt][3] = PERM_HI(p3.x, p3.y); al[mt][3] = PERM_LO(p3.x, p3.y);
            }
            #pragma unroll
            for (int nt = 0; nt < 2; nt++) {
                int nn = nq*16 + nt*8 + g;
                int kk = ks*16 + 2*t;
                uint32_t q0 = Bs[kk*68 + nn];
                uint32_t q1 = Bs[(kk+1)*68 + nn];
                uint32_t q2 = Bs[(kk+8)*68 + nn];
                uint32_t q3 = Bs[(kk+9)*68 + nn];
                uint32_t bfh[2] = {PERM_HI(q0, q1), PERM_HI(q2, q3)};
                uint32_t bfl[2] = {PERM_LO(q0, q1), PERM_LO(q2, q3)};
                #pragma unroll
                for (int mt = 0; mt < 2; mt++) {
                    mma_bf16(acc[mt][nt], ah[mt], bfh);
                    mma_bf16(acc[mt][nt], ah[mt], bfl);
                    mma_bf16(acc[mt][nt], al[mt], bfh);
                }
            }
        }
        __syncthreads();
    }

    #pragma unroll
    for (int mt = 0; mt < 2; mt++) {
        int row = m0 + mw*32 + mt*16 + g;
        #pragma unroll
        for (int nt = 0; nt < 2; nt++) {
            int col = n0 + nq*16 + nt*8 + 2*t;
            float b0 = bias[col], b1 = bias[col+1];
            float v0 = acc[mt][nt][0] + b0, v1 = acc[mt][nt][1] + b1;
            float v2 = acc[mt][nt][2] + b0, v3 = acc[mt][nt][3] + b1;
            if (mode == 0) {
                float* C = (float*)Cv;
                C[(size_t)row*N + col]       = v0;
                C[(size_t)row*N + col + 1]   = v1;
                C[(size_t)(row+8)*N + col]     = v2;
                C[(size_t)(row+8)*N + col + 1] = v3;
            } else {
                uint32_t* C = (uint32_t*)Cv;
                C[(size_t)row*N + col]       = bf16_split_elem(v0);
                C[(size_t)row*N + col + 1]   = bf16_split_elem(v1);
                C[(size_t)(row+8)*N + col]     = bf16_split_elem(v2);
                C[(size_t)(row+8)*N + col + 1] = bf16_split_elem(v3);
            }
        }
    }
}

// ---------------- tensor-core gated half-projection + SiLU ----------------
// CTA tile 64 rows x 32 cols (one half-head), K=128, 8 warps (2m x 4 n8).
__global__ __launch_bounds__(256) void mma_gated_kernel(
    const float* __restrict__ X,
    const float* __restrict__ W1, const float* __restrict__ b1,
    const float* __restrict__ W2, const float* __restrict__ b2,
    void* __restrict__ Yv, int packed)
{
    __shared__ uint32_t As[64*40];   // [m][k] packed
    __shared__ uint32_t Bs[32*36];   // [k][n] packed
    const int c0   = blockIdx.x * 32;
    const int head = c0 >> 6;
    const int is2  = (c0 >> 5) & 1;
    const float* W  = is2 ? W2 : W1;
    const float* bb = is2 ? b2 : b1;
    const int wc0 = head * 32;
    const float* Ain = X + (is2 ? 128 : 0);
    const int m0 = blockIdx.y * 64;
    const int tid = threadIdx.x, lane = tid & 31, w = tid >> 5;
    const int g = lane >> 2, t = lane & 3;
    const int mw = w >> 2, nq = w & 3;

    float aReg[8], bReg[4];
    #pragma unroll
    for (int i = 0; i < 8; i++) {
        int idx = 256*i + tid;
        aReg[i] = Ain[(size_t)(m0 + (idx >> 5)) * 256 + (idx & 31)];
    }
    #pragma unroll
    for (int i = 0; i < 4; i++) {
        int idx = 256*i + tid;
        bReg[i] = W[(size_t)(idx >> 5) * HALF_OUT + wc0 + (idx & 31)];
    }
    float acc[2][4] = {};

    for (int k0 = 0; k0 < 128; k0 += 32) {
        #pragma unroll
        for (int i = 0; i < 8; i++) {
            int idx = 256*i + tid;
            As[(idx >> 5)*40 + (idx & 31)] = bf16_split_elem(aReg[i]);
        }
        #pragma unroll
        for (int i = 0; i < 4; i++) {
            int idx = 256*i + tid;
            Bs[(idx >> 5)*36 + (idx & 31)] = bf16_split_elem(bReg[i]);
        }
        __syncthreads();
        if (k0 + 32 < 128) {
            #pragma unroll
            for (int i = 0; i < 8; i++) {
                int idx = 256*i + tid;
                aReg[i] = Ain[(size_t)(m0 + (idx >> 5)) * 256 + k0 + 32 + (idx & 31)];
            }
            #pragma unroll
            for (int i = 0; i < 4; i++) {
                int idx = 256*i + tid;
                bReg[i] = W[(size_t)(k0 + 32 + (idx >> 5)) * HALF_OUT + wc0 + (idx & 31)];
            }
        }
        #pragma unroll
        for (int ks = 0; ks < 2; ks++) {
            uint32_t ah[2][4], al[2][4];
            #pragma unroll
            for (int mt = 0; mt < 2; mt++) {
                int r = mw*32 + mt*16 + g;
                int d = ks*16 + 2*t;
                uint2 p0 = *(const uint2*)&As[r*40 + d];
                uint2 p1 = *(const uint2*)&As[(r+8)*40 + d];
                uint2 p2 = *(const uint2*)&As[r*40 + d + 8];
                uint2 p3 = *(const uint2*)&As[(r+8)*40 + d + 8];
                ah[mt][0] = PERM_HI(p0.x, p0.y); al[mt][0] = PERM_LO(p0.x, p0.y);
                ah[mt][1] = PERM_HI(p1.x, p1.y); al[mt][1] = PERM_LO(p1.x, p1.y);
                ah[mt][2] = PERM_HI(p2.x, p2.y); al[mt][2] = PERM_LO(p2.x, p2.y);
                ah[mt][3] = PERM_HI(p3.x, p3.y); al[mt][3] = PERM_LO(p3.x, p3.y);
            }
            {
                int nn = nq*8 + g;
                int kk = ks*16 + 2*t;
                uint32_t q0 = Bs[kk*36 + nn];
                uint32_t q1 = Bs[(kk+1)*36 + nn];
                uint32_t q2 = Bs[(kk+8)*36 + nn];
                uint32_t q3 = Bs[(kk+9)*36 + nn];
                uint32_t bfh[2] = {PERM_HI(q0, q1), PERM_HI(q2, q3)};
                uint32_t bfl[2] = {PERM_LO(q0, q1), PERM_LO(q2, q3)};
                #pragma unroll
                for (int mt = 0; mt < 2; mt++) {
                    mma_bf16(acc[mt], ah[mt], bfh);
                    mma_bf16(acc[mt], ah[mt], bfl);
                    mma_bf16(acc[mt], al[mt], bfh);
                }
            }
        }
        __syncthreads();
    }

    #pragma unroll
    for (int mt = 0; mt < 2; mt++) {
        int row = m0 + mw*32 + mt*16 + g;
        int col = nq*8 + 2*t;
        float b0 = bb[wc0 + col], b1 = bb[wc0 + col + 1];
        float v[4] = {acc[mt][0] + b0, acc[mt][1] + b1, acc[mt][2] + b0, acc[mt][3] + b1};
        #pragma unroll
        for (int j = 0; j < 4; j++) v[j] = v[j] / (1.0f + __expf(-v[j]));
        if (packed) {
            uint32_t* Yp = (uint32_t*)Yv;
            Yp[(size_t)row*DEXP + c0 + col]       = bf16_split_elem(v[0]);
            Yp[(size_t)row*DEXP + c0 + col + 1]   = bf16_split_elem(v[1]);
            Yp[(size_t)(row+8)*DEXP + c0 + col]     = bf16_split_elem(v[2]);
            Yp[(size_t)(row+8)*DEXP + c0 + col + 1] = bf16_split_elem(v[3]);
        } else {
            float* Yp = (float*)Yv;
            Yp[(size_t)row*DEXP + c0 + col]       = v[0];
            Yp[(size_t)row*DEXP + c0 + col + 1]   = v[1];
            Yp[(size_t)(row+8)*DEXP + c0 + col]     = v[2];
            Yp[(size_t)(row+8)*DEXP + c0 + col + 1] = v[3];
        }
    }
}

// ---------------- fused attention (bf16x3, 512 threads = 16 warps) ----------------
__global__ __launch_bounds__(512) void attn_kernel(
    const uint32_t* __restrict__ Qps, const uint32_t* __restrict__ Vps,
    const float* __restrict__ Uc, float* __restrict__ attn_out,
    float* __restrict__ Gout)
{
    extern __shared__ float sm[];
    float*    Sf  = sm;
    uint32_t* Su  = (uint32_t*)sm;
    uint32_t* buf = (uint32_t*)(sm + 32*SPITCH);
    uint32_t* Qb  = buf + 128*KPITCH;
    float*    R   = sm;

    const int r0 = blockIdx.x * 32;
    const int h  = blockIdx.y, b = blockIdx.z;
    const int tid  = threadIdx.x;
    const int lane = tid & 31;
    const int w    = tid >> 5;
    const int g    = lane >> 2;
    const int t    = lane & 3;
    const float scale = 0.17677669529663687f;

    #pragma unroll
    for (int i = 0; i < 2; i++) {
        int idx = 512*i + tid;
        int r = idx >> 5, d = idx & 31;
        Qb[r*QPITCH + d] = Qps[((size_t)(r0 + r) * BSZ + b) * DQK + h*DATT + d];
    }
    uint32_t kreg[8];
    #pragma unroll
    for (int i = 0; i < 8; i++) {
        int idx = 512*i + tid;
        int key = idx >> 5, d = idx & 31;
        kreg[i] = Qps[((size_t)key * BSZ + b) * DQK + h*DATT + d];
    }
    __syncthreads();

    uint32_t qa_hi[2][2][4], qa_lo[2][2][4];
    #pragma unroll
    for (int mt = 0; mt < 2; mt++) {
        int r = mt*16 + g;
        #pragma unroll
        for (int ks = 0; ks < 2; ks++) {
            int d = ks*16 + 2*t;
            uint2 p0 = *(const uint2*)&Qb[r*QPITCH + d];
            uint2 p1 = *(const uint2*)&Qb[(r+8)*QPITCH + d];
            uint2 p2 = *(const uint2*)&Qb[r*QPITCH + d + 8];
            uint2 p3 = *(const uint2*)&Qb[(r+8)*QPITCH + d + 8];
            qa_hi[mt][ks][0] = PERM_HI(p0.x, p0.y); qa_lo[mt][ks][0] = PERM_LO(p0.x, p0.y);
            qa_hi[mt][ks][1] = PERM_HI(p1.x, p1.y); qa_lo[mt][ks][1] = PERM_LO(p1.x, p1.y);
            qa_hi[mt][ks][2] = PERM_HI(p2.x, p2.y); qa_lo[mt][ks][2] = PERM_LO(p2.x, p2.y);
            qa_hi[mt][ks][3] = PERM_HI(p3.x, p3.y); qa_lo[mt][ks][3] = PERM_LO(p3.x, p3.y);
        }
    }

    for (int kt = 0; kt < 8; kt++) {
        #pragma unroll
        for (int i = 0; i < 8; i++) {
            int idx = 512*i + tid;
            buf[(idx >> 5)*KPITCH + (idx & 31)] = kreg[i];
        }
        __syncthreads();
        if (kt < 7) {
            int base = (kt + 1) * 128;
            #pragma unroll
            for (int i = 0; i < 8; i++) {
                int idx = 512*i + tid;
                int key = base + (idx >> 5), d = idx & 31;
                kreg[i] = Qps[((size_t)key * BSZ + b) * DQK + h*DATT + d];
            }
        }
        uint32_t bh[2][2], bl[2][2];
        {
            int key = w*8 + g;
            #pragma unroll
            for (int ks = 0; ks < 2; ks++) {
                int d = ks*16 + 2*t;
                uint2 p0 = *(const uint2*)&buf[key*KPITCH + d];
                uint2 p1 = *(const uint2*)&buf[key*KPITCH + d + 8];
                bh[ks][0] = PERM_HI(p0.x, p0.y); bl[ks][0] = PERM_LO(p0.x, p0.y);
                bh[ks][1] = PERM_HI(p1.x, p1.y); bl[ks][1] = PERM_LO(p1.x, p1.y);
            }
        }
        __syncthreads();
        #pragma unroll
        for (int mt = 0; mt < 2; mt++) {
            float c[4] = {0.f, 0.f, 0.f, 0.f};
            #pragma unroll
            for (int ks = 0; ks < 2; ks++) {
                mma_bf16(c, qa_hi[mt][ks], bh[ks]);
                mma_bf16(c, qa_hi[mt][ks], bl[ks]);
                mma_bf16(c, qa_lo[mt][ks], bh[ks]);
            }
            int row = mt*16 + g;
            int col = kt*128 + w*8 + 2*t;
            *(float2*)&Sf[row*SPITCH + col]     = make_float2(c[0]*scale, c[1]*scale);
            *(float2*)&Sf[(row+8)*SPITCH + col] = make_float2(c[2]*scale, c[3]*scale);
        }
    }
    __syncthreads();

    uint4 vreg[2];
    #pragma unroll
    for (int i = 0; i < 2; i++) {
        int f = 512*i + tid;
        int key = f >> 4, c4 = f & 15;
        vreg[i] = *(const uint4*)&Vps[((size_t)key * BSZ + b) * DEXP + h*HDIM + c4*4];
    }

    {
        for (int rr = 0; rr < 2; rr++) {
            int r = 2*w + rr;
            float* row = Sf + r*SPITCH;
            uint32_t* urow = Su + r*SPITCH;
            float m = -1e30f;
            for (int k = lane; k < 1024; k += 32) m = fmaxf(m, row[k]);
            #pragma unroll
            for (int o = 16; o; o >>= 1) m = fmaxf(m, __shfl_xor_sync(0xffffffffu, m, o));
            float s = 0.f;
            for (int k = lane; k < 1024; k += 32) {
                float e = __expf(row[k] - m);
                row[k] = e; s += e;
            }
            #pragma unroll
            for (int o = 16; o; o >>= 1) s += __shfl_xor_sync(0xffffffffu, s, o);
            float inv = 1.0f / s;
            __syncwarp();
            float* gp = attn_out ? attn_out + (((size_t)(b*NHEAD + h) * LL + (r0 + r)) * LL) : nullptr;
            #pragma unroll 4
            for (int i = 0; i < 16; i++) {
                int k = 2*lane + 64*i;
                float p0 = row[k] * inv, p1 = row[k+1] * inv;
                if (gp) *(float2*)&gp[k] = make_float2(p0, p1);
                urow[k]   = bf16_split_elem(p0);
                urow[k+1] = bf16_split_elem(p1);
            }
        }
    }

    const int ks = w >> 2;
    const int nq = w & 3;
    float cav[2][2][4] = {};
    for (int vt = 0; vt < 16; vt++) {
        #pragma unroll
        for (int i = 0; i < 2; i++) {
            int f = 512*i + tid;
            int key = f >> 4, c4 = f & 15;
            *(uint4*)&buf[key*VPITCH + c4*4] = vreg[i];
        }
        __syncthreads();
        if (vt < 15) {
            int base = (vt + 1) * 64;
            #pragma unroll
            for (int i = 0; i < 2; i++) {
                int f = 512*i + tid;
                int key = base + (f >> 4), c4 = f & 15;
                vreg[i] = *(const uint4*)&Vps[((size_t)key * BSZ + b) * DEXP + h*HDIM + c4*4];
            }
        }
        uint32_t ah[2][4], al[2][4];
        #pragma unroll
        for (int mt = 0; mt < 2; mt++) {
            int r = mt*16 + g;
            int d = vt*64 + ks*16 + 2*t;
            uint2 p0 = *(const uint2*)&Su[r*SPITCH + d];
            uint2 p1 = *(const uint2*)&Su[(r+8)*SPITCH + d];
            uint2 p2 = *(const uint2*)&Su[r*SPITCH + d + 8];
            uint2 p3 = *(const uint2*)&Su[(r+8)*SPITCH + d + 8];
            ah[mt][0] = PERM_HI(p0.x, p0.y); al[mt][0] = PERM_LO(p0.x, p0.y);
            ah[mt][1] = PERM_HI(p1.x, p1.y); al[mt][1] = PERM_LO(p1.x, p1.y);
            ah[mt][2] = PERM_HI(p2.x, p2.y); al[mt][2] = PERM_LO(p2.x, p2.y);
            ah[mt][3] = PERM_HI(p3.x, p3.y); al[mt][3] = PERM_LO(p3.x, p3.y);
        }
        #pragma unroll
        for (int nt = 0; nt < 2; nt++) {
            int nn = nq*16 + nt*8 + g;
            int kk = ks*16 + 2*t;
            uint32_t q0 = buf[kk*VPITCH + nn];
            uint32_t q1 = buf[(kk+1)*VPITCH + nn];
            uint32_t q2 = buf[(kk+8)*VPITCH + nn];
            uint32_t q3 = buf[(kk+9)*VPITCH + nn];
            uint32_t bfh[2], bfl[2];
            bfh[0] = PERM_HI(q0, q1); bfl[0] = PERM_LO(q0, q1);
            bfh[1] = PERM_HI(q2, q3); bfl[1] = PERM_LO(q2, q3);
            #pragma unroll
            for (int mt = 0; mt < 2; mt++) {
                mma_bf16(cav[mt][nt], ah[mt], bfh);
                mma_bf16(cav[mt][nt], ah[mt], bfl);
                mma_bf16(cav[mt][nt], al[mt], bfh);
            }
        }
        __syncthreads();
    }

    #pragma unroll
    for (int mt = 0; mt < 2; mt++) {
        int row = mt*16 + g;
        #pragma unroll
        for (int nt = 0; nt < 2; nt++) {
            int col = nq*16 + nt*8 + 2*t;
            *(float2*)&R[((ks*32 + row)*64) + col]     = make_float2(cav[mt][nt][0], cav[mt][nt][1]);
            *(float2*)&R[((ks*32 + row + 8)*64) + col] = make_float2(cav[mt][nt][2], cav[mt][nt][3]);
        }
    }
    __syncthreads();

    {
        int rr = tid >> 4;
        int c  = 2*(tid & 15);
        float2 s  = make_float2(0.f, 0.f);
        float2 s2 = make_float2(0.f, 0.f);
        #pragma unroll
        for (int kq = 0; kq < 4; kq++) {
            float2 p  = *(const float2*)&R[((kq*32 + rr)*64) + c];
            float2 p2 = *(const float2*)&R[((kq*32 + rr)*64) + c + 32];
            s.x += p.x;  s.y += p.y;
            s2.x += p2.x; s2.y += p2.y;
        }
        size_t gb = ((size_t)(r0 + rr) * BSZ + b) * DEXP + h*HDIM;
        float2 u  = *(const float2*)&Uc[gb + c];
        *(float2*)&Gout[gb + c] = make_float2(s.x*u.x, s.y*u.y);
        float2 u2 = *(const float2*)&Uc[gb + c + 32];
        *(float2*)&Gout[gb + c + 32] = make_float2(s2.x*u2.x, s2.y*u2.y);
    }
}

// ---------------- depthwise 5x5 conv, row-tiled ----------------
// grid (16 ctile, 4 rowtile, BSZ); 256 threads; dynamic smem ~54 KB
__global__ __launch_bounds__(256) void dwconv_kernel(
    const float* __restrict__ X, const float* __restrict__ Wc, float* __restrict__ Y)
{
    extern __shared__ float sm[];
    float* xs = sm;              // [12*32][33] local rows r0-2..r0+9
    float* ws = sm + 384*33;     // [32][25]
    const int c0 = blockIdx.x * 32;
    const int r0 = blockIdx.y * 8;
    const int b  = blockIdx.z;
    const int tid = threadIdx.x;

    #pragma unroll
    for (int i = 0; i < 48; i++) {
        int idx = tid + 256*i;
        int lp = idx >> 5, c = idx & 31;
        int gr = r0 - 2 + (lp >> 5);
        int j  = lp & 31;
        float v = 0.f;
        if (gr >= 0 && gr < 32)
            v = X[((size_t)(gr*32 + j) * BSZ + b) * DEXP + c0 + c];
        xs[lp*33 + c] = v;
    }
    for (int idx = tid; idx < 32*25; idx += 256) {
        int c = idx / 25, tt = idx % 25;
        ws[c*25 + tt] = Wc[(size_t)(c0 + c) * 25 + tt];
    }
    __syncthreads();

    const int c = tid & 31, pr = tid >> 5;
    for (int s = 0; s < 32; s++) {
        int pos = pr + 8*s;          // 0..255
        int rl = pos >> 5, j = pos & 31;
        float acc = 0.f;
        #pragma unroll
        for (int di = 0; di < 5; di++) {
            int li = rl + di;        // local input row index
            #pragma unroll
            for (int dj = 0; dj < 5; dj++) {
                int jj = j + dj - 2;
                if (jj < 0 || jj >= 32) continue;
                acc += xs[(li*32 + jj)*33 + c] * ws[c*25 + di*5 + dj];
            }
        }
        Y[((size_t)((r0 + rl)*32 + j) * BSZ + b) * DEXP + c0 + c] = acc;
    }
}

// ---------------- launch ----------------
extern "C" void kernel_launch(void* const* d_in, const int* in_sizes, int n_in,
                              void* d_out, int out_size)
{
    const float* Q   = (const float*)d_in[0];
    const float* V   = (const float*)d_in[2];
    const float* U   = (const float*)d_in[3];
    const float* Wqk = (const float*)d_in[4];
    const float* bqk = (const float*)d_in[5];
    const float* Wv1 = (const float*)d_in[6];
    const float* bv1 = (const float*)d_in[7];
    const float* Wv2 = (const float*)d_in[8];
    const float* bv2 = (const float*)d_in[9];
    const float* Wu1 = (const float*)d_in[10];
    const float* bu1 = (const float*)d_in[11];
    const float* Wu2 = (const float*)d_in[12];
    const float* bu2 = (const float*)d_in[13];
    const float* Wcv = (const float*)d_in[14];
    const float* Wp  = (const float*)d_in[15];
    const float* bp  = (const float*)d_in[16];

    float* out  = (float*)d_out;
    float* attn = (out_size > MROWS*DQK) ? out + (size_t)MROWS*DQK : nullptr;

    uint32_t *Qps, *Vps;
    float *Uc, *G, *Y;
    cudaGetSymbolAddress((void**)&Qps, g_Qps);
    cudaGetSymbolAddress((void**)&Vps, g_Vps);
    cudaGetSymbolAddress((void**)&Uc,  g_Uc);
    cudaGetSymbolAddress((void**)&G,   g_G);
    cudaGetSymbolAddress((void**)&Y,   g_Y);

    const size_t ATTN_SMEM = (size_t)(32*SPITCH + 128*KPITCH + 32*QPITCH) * 4; // ~158 KB
    const size_t CONV_SMEM = (size_t)(384*33 + 32*25) * sizeof(float);         // ~54 KB
    cudaFuncSetAttribute(attn_kernel,   cudaFuncAttributeMaxDynamicSharedMemorySize, (int)ATTN_SMEM);
    cudaFuncSetAttribute(dwconv_kernel, cudaFuncAttributeMaxDynamicSharedMemorySize, (int)CONV_SMEM);

    // 1) Qp = Q @ Wqk + bqk -> packed u32 (tensor cores)
    {
        dim3 grid(DQK/64, MROWS/64);
        mma_gemm_kernel<<<grid, 256>>>(Q, Wqk, bqk, Qps, MROWS, DQK, DQK, 1);
    }
    // 2) Vc packed, Uc fp32 (tensor cores)
    {
        dim3 grid(16, MROWS/64);
        mma_gated_kernel<<<grid, 256>>>(V, Wv1, bv1, Wv2, bv2, Vps, 1);
        mma_gated_kernel<<<grid, 256>>>(U, Wu1, bu1, Wu2, bu2, Uc, 0);
    }
    // 3) attention
    {
        dim3 grid(LL/32, NHEAD, BSZ);
        attn_kernel<<<grid, 512, ATTN_SMEM>>>(Qps, Vps, Uc, attn, G);
    }
    // 4) depthwise conv (row-tiled)
    {
        dim3 grid(16, 4, BSZ);
        dwconv_kernel<<<grid, 256, CONV_SMEM>>>(G, Wcv, Y);
    }
    // 5) outputs = Y @ Wp + bp (tensor cores)
    {
        dim3 grid(DQK/64, MROWS/64);
        mma_gemm_kernel<<<grid, 256>>>(Y, Wp, bp, out, MROWS, DQK, DEXP, 0);
    }
}